// round 1
// baseline (speedup 1.0000x reference)
#include <cuda_runtime.h>
#include <math.h>

// Input order (metadata.txt):
// 0 hidden_states f32 [2,2048,1024]
// 1 attention_mask f32 [2,1,1,2048]
// 2 local_attention_mask i32 [2,1,2048,2048]
// 3 gate_outputs f32 [2,16,2048,1]
// 4 Wq f32 [1024,1024]   5 bq f32 [1024]
// 6 Wk                   7 bk
// 8 Wv                   9 bv
// output f32 [2,2048,1024]

#define B_  2
#define S_  2048
#define H_  1024
#define NH_ 16
#define DH_ 64

// Scratch (allocation-free rule: __device__ globals)
__device__ float g_q[B_*NH_*S_*DH_];
__device__ float g_k[B_*NH_*S_*DH_];
__device__ float g_v[B_*NH_*S_*DH_];

// ---------------------------------------------------------------------------
// Fused QKV projection: out = X @ W^T + b, written in [B,NH,S,DH] layout.
// 64x64x16 tiles, 256 threads, 4x4 micro-tile per thread, reg-prefetch pipeline.
// ---------------------------------------------------------------------------
__global__ __launch_bounds__(256) void qkv_gemm(
    const float* __restrict__ X,
    const float* __restrict__ Wq, const float* __restrict__ bq,
    const float* __restrict__ Wk, const float* __restrict__ bk,
    const float* __restrict__ Wv, const float* __restrict__ bv)
{
    __shared__ float As[16][68];
    __shared__ float Bs[16][68];

    const int z = blockIdx.z;
    const float* __restrict__ W    = (z == 0) ? Wq : (z == 1) ? Wk : Wv;
    const float* __restrict__ bias = (z == 0) ? bq : (z == 1) ? bk : bv;
    float* __restrict__ out        = (z == 0) ? g_q : (z == 1) ? g_k : g_v;

    const int m0 = blockIdx.y * 64;
    const int n0 = blockIdx.x * 64;
    const int tid = threadIdx.x;
    const int lr = tid >> 2;          // 0..63 : row within tile for loading
    const int lc = (tid & 3) * 4;     // 0,4,8,12 : k-offset within 16
    const int tx = tid & 15;          // micro-tile col group
    const int ty = tid >> 4;          // micro-tile row group

    float acc[4][4] = {};

    const float* arow = X + (m0 + lr) * H_ + lc;
    const float* wrow = W + (n0 + lr) * H_ + lc;

    float4 a = *(const float4*)(arow);
    float4 w = *(const float4*)(wrow);

    for (int k0 = 0; k0 < H_; k0 += 16) {
        __syncthreads();
        As[lc+0][lr] = a.x; As[lc+1][lr] = a.y; As[lc+2][lr] = a.z; As[lc+3][lr] = a.w;
        Bs[lc+0][lr] = w.x; Bs[lc+1][lr] = w.y; Bs[lc+2][lr] = w.z; Bs[lc+3][lr] = w.w;
        if (k0 + 16 < H_) {   // prefetch next k-slab while this one computes
            a = *(const float4*)(arow + k0 + 16);
            w = *(const float4*)(wrow + k0 + 16);
        }
        __syncthreads();
        #pragma unroll
        for (int k = 0; k < 16; k++) {
            float4 av  = *(const float4*)(&As[k][ty * 4]);
            float4 bv4 = *(const float4*)(&Bs[k][tx * 4]);
            acc[0][0] += av.x*bv4.x; acc[0][1] += av.x*bv4.y; acc[0][2] += av.x*bv4.z; acc[0][3] += av.x*bv4.w;
            acc[1][0] += av.y*bv4.x; acc[1][1] += av.y*bv4.y; acc[1][2] += av.y*bv4.z; acc[1][3] += av.y*bv4.w;
            acc[2][0] += av.z*bv4.x; acc[2][1] += av.z*bv4.y; acc[2][2] += av.z*bv4.z; acc[2][3] += av.z*bv4.w;
            acc[3][0] += av.w*bv4.x; acc[3][1] += av.w*bv4.y; acc[3][2] += av.w*bv4.z; acc[3][3] += av.w*bv4.w;
        }
    }

    // n-tile == exactly one head (TN == DH == 64)
    const int h = n0 >> 6;
    float4 bb = *(const float4*)(&bias[n0 + tx * 4]);
    #pragma unroll
    for (int i = 0; i < 4; i++) {
        const int m  = m0 + ty * 4 + i;
        const int bI = m >> 11;            // /S_
        const int s  = m & (S_ - 1);
        float4 o;
        o.x = acc[i][0] + bb.x; o.y = acc[i][1] + bb.y;
        o.z = acc[i][2] + bb.z; o.w = acc[i][3] + bb.w;
        *(float4*)&out[(((size_t)(bI*NH_ + h))*S_ + s)*DH_ + tx*4] = o;
    }
}

// ---------------------------------------------------------------------------
// Dual-branch flash attention with gating.
// Block = (head, q-tile of 64, batch). 256 threads: thread = (row r, quad qd),
// owns 16 score columns / 16 output dims (c0 = qd*16).
// Shared running max m for both branches:
//   e    = exp(s - m)
//   e_g  = e * exp(amask[k])           (exp(amask) precomputed per key)
//   e_l  = local_mask ? e : 0          (mask folded into sign of smem p-tile)
// ---------------------------------------------------------------------------
#define QS_OFF 0            // 64*68
#define KT_OFF 4352         // 64*64  (kT[d][c])
#define VS_OFF 8448         // 64*64  (vs[c][d])
#define PT_OFF 12544        // 64*65  (signed probs)
#define EA_OFF 16704        // 64     (exp(amask))
#define SMEM_FLOATS 16768   // 67072 bytes

__global__ __launch_bounds__(256) void attn_kernel(
    const float* __restrict__ amask, const int* __restrict__ lmask,
    const float* __restrict__ gate,  float* __restrict__ out)
{
    extern __shared__ float smf[];
    float* qs = smf + QS_OFF;
    float* kT = smf + KT_OFF;
    float* vs = smf + VS_OFF;
    float* pt = smf + PT_OFF;
    float* ea = smf + EA_OFF;

    const int h  = blockIdx.x;
    const int qt = blockIdx.y;
    const int b  = blockIdx.z;
    const int tid = threadIdx.x;
    const int r  = tid >> 2;
    const int qd = tid & 3;
    const int c0 = qd * 16;

    const size_t base = ((size_t)(b*NH_ + h)) * S_ * DH_;
    const float* Q = g_q + base;
    const float* K = g_k + base;
    const float* V = g_v + base;

    // Load Q tile (stride 68 kills LDS bank conflicts on the d-broadcast read)
    {
        const float* qp = Q + ((size_t)(qt*64 + r))*64 + c0;
        #pragma unroll
        for (int i = 0; i < 4; i++)
            *(float4*)&qs[r*68 + c0 + 4*i] = *(const float4*)(qp + 4*i);
    }

    float accg[16], accl[16];
    #pragma unroll
    for (int i = 0; i < 16; i++) { accg[i] = 0.f; accl[i] = 0.f; }
    float mrow = -INFINITY, lg = 0.f, ll = 0.f;

    const int* lrow = lmask + ((size_t)(b*S_) + (qt*64 + r)) * S_ + c0;

    for (int kt = 0; kt < S_; kt += 64) {
        // per-key exp(additive mask) for this tile
        if (tid < 64) ea[tid] = __expf(amask[b*S_ + kt + tid]);

        // Load K (transposed into kT[d][c]) and V (vs[c][d]); this thread acts
        // as loader for key-row r, d-range c0..c0+15.
        {
            const float* kp = K + ((size_t)(kt + r))*64 + c0;
            float4 ka = *(const float4*)(kp);
            float4 kb = *(const float4*)(kp + 4);
            float4 kc = *(const float4*)(kp + 8);
            float4 kd = *(const float4*)(kp + 12);
            kT[(c0+ 0)*64 + r] = ka.x; kT[(c0+ 1)*64 + r] = ka.y; kT[(c0+ 2)*64 + r] = ka.z; kT[(c0+ 3)*64 + r] = ka.w;
            kT[(c0+ 4)*64 + r] = kb.x; kT[(c0+ 5)*64 + r] = kb.y; kT[(c0+ 6)*64 + r] = kb.z; kT[(c0+ 7)*64 + r] = kb.w;
            kT[(c0+ 8)*64 + r] = kc.x; kT[(c0+ 9)*64 + r] = kc.y; kT[(c0+10)*64 + r] = kc.z; kT[(c0+11)*64 + r] = kc.w;
            kT[(c0+12)*64 + r] = kd.x; kT[(c0+13)*64 + r] = kd.y; kT[(c0+14)*64 + r] = kd.z; kT[(c0+15)*64 + r] = kd.w;
            const float* vp = V + ((size_t)(kt + r))*64 + c0;
            #pragma unroll
            for (int i = 0; i < 4; i++)
                *(float4*)&vs[r*64 + c0 + 4*i] = *(const float4*)(vp + 4*i);
        }

        // Local-mask bits for this thread's 16 columns (LDG overlaps with sync)
        int4 lm0 = *(const int4*)(lrow + kt);
        int4 lm1 = *(const int4*)(lrow + kt + 4);
        int4 lm2 = *(const int4*)(lrow + kt + 8);
        int4 lm3 = *(const int4*)(lrow + kt + 12);

        __syncthreads();

        // ---- scores: s[c] = q[r,:] . k[c,:] ----
        float sc[16];
        #pragma unroll
        for (int i = 0; i < 16; i++) sc[i] = 0.f;
        #pragma unroll 8
        for (int d = 0; d < 64; d++) {
            float qv = qs[r*68 + d];
            const float* krow = &kT[d*64 + c0];
            #pragma unroll
            for (int i = 0; i < 4; i++) {
                float4 k4 = *(const float4*)(krow + 4*i);
                sc[4*i+0] += qv*k4.x; sc[4*i+1] += qv*k4.y;
                sc[4*i+2] += qv*k4.z; sc[4*i+3] += qv*k4.w;
            }
        }

        // ---- online softmax (shared max for both branches) ----
        float tmax = -INFINITY;
        #pragma unroll
        for (int i = 0; i < 16; i++) { sc[i] *= 0.125f; tmax = fmaxf(tmax, sc[i]); }
        tmax = fmaxf(tmax, __shfl_xor_sync(0xffffffffu, tmax, 1));
        tmax = fmaxf(tmax, __shfl_xor_sync(0xffffffffu, tmax, 2));

        float newm = fmaxf(mrow, tmax);
        float corr = __expf(mrow - newm);    // exp(-inf)=0 handles first tile
        mrow = newm;
        lg *= corr; ll *= corr;
        #pragma unroll
        for (int i = 0; i < 16; i++) { accg[i] *= corr; accl[i] *= corr; }

        int mk[16] = { lm0.x, lm0.y, lm0.z, lm0.w,
                       lm1.x, lm1.y, lm1.z, lm1.w,
                       lm2.x, lm2.y, lm2.z, lm2.w,
                       lm3.x, lm3.y, lm3.z, lm3.w };
        float sg = 0.f, sl = 0.f;
        #pragma unroll
        for (int i = 0; i < 16; i++) {
            float pe = __expf(sc[i] - mrow);
            sg += pe * ea[c0 + i];
            float pv = mk[i] ? pe : -pe;     // fold local mask into sign bit
            sl += fmaxf(pv, 0.f);
            pt[r*65 + c0 + i] = pv;
        }
        sg += __shfl_xor_sync(0xffffffffu, sg, 1);
        sg += __shfl_xor_sync(0xffffffffu, sg, 2);
        sl += __shfl_xor_sync(0xffffffffu, sl, 1);
        sl += __shfl_xor_sync(0xffffffffu, sl, 2);
        lg += sg; ll += sl;

        __syncthreads();

        // ---- PV: both accumulators in one sweep ----
        #pragma unroll 4
        for (int c = 0; c < 64; c++) {
            float p   = pt[r*65 + c];
            float wg  = fabsf(p) * ea[c];
            float wl  = fmaxf(p, 0.f);
            const float* vrow = &vs[c*64 + c0];
            #pragma unroll
            for (int i = 0; i < 4; i++) {
                float4 v4 = *(const float4*)(vrow + 4*i);
                accg[4*i+0] += wg*v4.x; accg[4*i+1] += wg*v4.y;
                accg[4*i+2] += wg*v4.z; accg[4*i+3] += wg*v4.w;
                accl[4*i+0] += wl*v4.x; accl[4*i+1] += wl*v4.y;
                accl[4*i+2] += wl*v4.z; accl[4*i+3] += wl*v4.w;
            }
        }
        __syncthreads();   // before next tile overwrites kT/vs/pt
    }

    // ---- gate + write out [B,S,H] ----
    const float g  = gate[((size_t)(b*NH_ + h))*S_ + qt*64 + r];
    const float ig = (1.f - g) / lg;
    const float il = g / ll;
    float* op = out + ((size_t)(b*S_ + qt*64 + r))*H_ + h*DH_ + c0;
    #pragma unroll
    for (int i = 0; i < 4; i++) {
        float4 o;
        o.x = accl[4*i+0]*il + accg[4*i+0]*ig;
        o.y = accl[4*i+1]*il + accg[4*i+1]*ig;
        o.z = accl[4*i+2]*il + accg[4*i+2]*ig;
        o.w = accl[4*i+3]*il + accg[4*i+3]*ig;
        *(float4*)(op + 4*i) = o;
    }
}

// ---------------------------------------------------------------------------
extern "C" void kernel_launch(void* const* d_in, const int* in_sizes, int n_in,
                              void* d_out, int out_size)
{
    const float* X     = (const float*)d_in[0];
    const float* amask = (const float*)d_in[1];
    const int*   lmask = (const int*)  d_in[2];
    const float* gate  = (const float*)d_in[3];
    const float* Wq    = (const float*)d_in[4];
    const float* bq    = (const float*)d_in[5];
    const float* Wk    = (const float*)d_in[6];
    const float* bk    = (const float*)d_in[7];
    const float* Wv    = (const float*)d_in[8];
    const float* bv    = (const float*)d_in[9];
    float* out = (float*)d_out;

    dim3 g1(H_/64, (B_*S_)/64, 3);
    qkv_gemm<<<g1, 256>>>(X, Wq, bq, Wk, bk, Wv, bv);

    cudaFuncSetAttribute(attn_kernel,
                         cudaFuncAttributeMaxDynamicSharedMemorySize,
                         SMEM_FLOATS * (int)sizeof(float));
    dim3 g2(NH_, S_/64, B_);   // head fastest -> lmask rows shared in L2 across heads
    attn_kernel<<<g2, 256, SMEM_FLOATS * sizeof(float)>>>(amask, lmask, gate, out);
}

// round 2
// speedup vs baseline: 2.4959x; 2.4959x over previous
#include <cuda_runtime.h>
#include <math.h>
#include <stdint.h>

// Inputs:
// 0 hidden_states f32 [2,2048,1024]
// 1 attention_mask f32 [2,1,1,2048]
// 2 local_attention_mask i32 [2,1,2048,2048]
// 3 gate_outputs f32 [2,16,2048,1]
// 4 Wq 5 bq 6 Wk 7 bk 8 Wv 9 bv
// out f32 [2,2048,1024]

#define B_  2
#define S_  2048
#define H_  1024
#define NH_ 16
#define DH_ 64

__device__ float g_q[B_*NH_*S_*DH_];
__device__ float g_k[B_*NH_*S_*DH_];
__device__ float g_v[B_*NH_*S_*DH_];

// ---------------- f32x2 packed helpers (sm_10x FFMA2 path) ----------------
__device__ __forceinline__ uint64_t bpack(float x) {
    uint64_t r;
    asm("mov.b64 %0, {%1, %1};" : "=l"(r) : "r"(__float_as_uint(x)));
    return r;
}
__device__ __forceinline__ void fma2(uint64_t& d, uint64_t a, uint64_t b) {
    asm("fma.rn.f32x2 %0, %1, %2, %0;" : "+l"(d) : "l"(a), "l"(b));
}
__device__ __forceinline__ void mul2(uint64_t& d, uint64_t a) {
    asm("mul.rn.f32x2 %0, %1, %0;" : "+l"(d) : "l"(a));
}
__device__ __forceinline__ float lo32(uint64_t v) { return __uint_as_float((uint32_t)v); }
__device__ __forceinline__ float hi32(uint64_t v) { return __uint_as_float((uint32_t)(v >> 32)); }

// ---------------------------------------------------------------------------
// QKV projection: out = X @ W^T + b -> [B,NH,S,DH].
// 128x128x8 tiles, 256 threads, 8x8 micro-tile (split 4+4), FFMA2 over n-pairs.
// ---------------------------------------------------------------------------
__global__ __launch_bounds__(256, 2) void qkv_gemm(
    const float* __restrict__ X,
    const float* __restrict__ Wq, const float* __restrict__ bq,
    const float* __restrict__ Wk, const float* __restrict__ bk,
    const float* __restrict__ Wv, const float* __restrict__ bv)
{
    __shared__ float As[8 * 132];
    __shared__ float Bs[8 * 132];

    const int z = blockIdx.z;
    const float* __restrict__ W    = (z == 0) ? Wq : (z == 1) ? Wk : Wv;
    const float* __restrict__ bias = (z == 0) ? bq : (z == 1) ? bk : bv;
    float* __restrict__ outp       = (z == 0) ? g_q : (z == 1) ? g_k : g_v;

    const int m0 = blockIdx.y * 128;
    const int n0 = blockIdx.x * 128;
    const int tid = threadIdx.x;
    const int tx = tid & 15;
    const int ty = tid >> 4;
    const int lrow = tid >> 1;
    const int lk4  = (tid & 1) * 4;

    const float* ap = X + (size_t)(m0 + lrow) * H_ + lk4;
    const float* bp = W + (size_t)(n0 + lrow) * H_ + lk4;

    float4 pa = *(const float4*)ap;
    float4 pb = *(const float4*)bp;

    uint64_t acc[8][4];
    #pragma unroll
    for (int i = 0; i < 8; i++)
        #pragma unroll
        for (int j = 0; j < 4; j++) acc[i][j] = 0ull;

    for (int k0 = 0; k0 < H_; k0 += 8) {
        __syncthreads();
        As[(lk4+0)*132 + lrow] = pa.x; As[(lk4+1)*132 + lrow] = pa.y;
        As[(lk4+2)*132 + lrow] = pa.z; As[(lk4+3)*132 + lrow] = pa.w;
        Bs[(lk4+0)*132 + lrow] = pb.x; Bs[(lk4+1)*132 + lrow] = pb.y;
        Bs[(lk4+2)*132 + lrow] = pb.z; Bs[(lk4+3)*132 + lrow] = pb.w;
        if (k0 + 8 < H_) {
            pa = *(const float4*)(ap + k0 + 8);
            pb = *(const float4*)(bp + k0 + 8);
        }
        __syncthreads();

        #pragma unroll
        for (int k = 0; k < 8; k++) {
            ulonglong2 b01 = *(const ulonglong2*)&Bs[k*132 + tx*4];
            ulonglong2 b23 = *(const ulonglong2*)&Bs[k*132 + 64 + tx*4];
            float4 a03 = *(const float4*)&As[k*132 + ty*4];
            float4 a47 = *(const float4*)&As[k*132 + 64 + ty*4];
            float am[8] = {a03.x, a03.y, a03.z, a03.w, a47.x, a47.y, a47.z, a47.w};
            #pragma unroll
            for (int i = 0; i < 8; i++) {
                uint64_t a2 = bpack(am[i]);
                fma2(acc[i][0], a2, b01.x);
                fma2(acc[i][1], a2, b01.y);
                fma2(acc[i][2], a2, b23.x);
                fma2(acc[i][3], a2, b23.y);
            }
        }
    }

    const int h0 = n0 >> 6;
    float4 bias0 = *(const float4*)&bias[n0 + tx*4];
    float4 bias1 = *(const float4*)&bias[n0 + 64 + tx*4];
    #pragma unroll
    for (int i = 0; i < 8; i++) {
        const int m  = m0 + ((i < 4) ? (ty*4 + i) : (64 + ty*4 + i - 4));
        const int bI = m >> 11;
        const int s  = m & (S_ - 1);
        float4 o0, o1;
        o0.x = lo32(acc[i][0]) + bias0.x; o0.y = hi32(acc[i][0]) + bias0.y;
        o0.z = lo32(acc[i][1]) + bias0.z; o0.w = hi32(acc[i][1]) + bias0.w;
        o1.x = lo32(acc[i][2]) + bias1.x; o1.y = hi32(acc[i][2]) + bias1.y;
        o1.z = lo32(acc[i][3]) + bias1.z; o1.w = hi32(acc[i][3]) + bias1.w;
        *(float4*)&outp[(((size_t)(bI*NH_ + h0  ))*S_ + s)*DH_ + tx*4] = o0;
        *(float4*)&outp[(((size_t)(bI*NH_ + h0+1))*S_ + s)*DH_ + tx*4] = o1;
    }
}

// ---------------------------------------------------------------------------
// Dual-branch flash attention, 4x4 register tiles + FFMA2.
// ea (exp of additive mask) and local mask folded into two smem prob tiles
// pg/pl at softmax time -> PV is two pure FFMA2 streams.
// ---------------------------------------------------------------------------
#define QT_OFF 0            // 64*64
#define KT_OFF 4096         // 64*64
#define VS_OFF 8192         // 64*68
#define PG_OFF 12544        // 64*68
#define PL_OFF 16896        // 64*68
#define EA_OFF 21248        // 64
#define SM_FLOATS 21312     // 85248 bytes

__global__ __launch_bounds__(256, 2) void attn_kernel(
    const float* __restrict__ amask, const int* __restrict__ lmask,
    const float* __restrict__ gate,  float* __restrict__ out)
{
    extern __shared__ float smf[];
    float* qT = smf + QT_OFF;
    float* kT = smf + KT_OFF;
    float* vs = smf + VS_OFF;
    float* pg = smf + PG_OFF;
    float* pl = smf + PL_OFF;
    float* ea = smf + EA_OFF;

    const int h  = blockIdx.x;
    const int qt = blockIdx.y;
    const int b  = blockIdx.z;
    const int tid = threadIdx.x;
    const int tx = tid & 15;
    const int ty = tid >> 4;
    const int lr  = tid & 63;
    const int lc0 = (tid >> 6) * 16;

    const size_t base = ((size_t)(b*NH_ + h)) * S_ * DH_;
    const float* K = g_k + base;
    const float* V = g_v + base;

    // Q tile -> qT[d][q], pre-scaled by 1/sqrt(DH)
    {
        const float* qp = g_q + base + (size_t)(qt*64 + lr)*64 + lc0;
        #pragma unroll
        for (int u = 0; u < 4; u++) {
            float4 v4 = *(const float4*)(qp + 4*u);
            kT[(lc0 + 4*u + 0)*64 + lr] = v4.x;  // stage through kT slot is unsafe; use qT
            (void)v4;
        }
    }
    // (redo cleanly into qT)
    {
        const float* qp = g_q + base + (size_t)(qt*64 + lr)*64 + lc0;
        #pragma unroll
        for (int u = 0; u < 4; u++) {
            float4 v4 = *(const float4*)(qp + 4*u);
            qT[(lc0 + 4*u + 0)*64 + lr] = v4.x * 0.125f;
            qT[(lc0 + 4*u + 1)*64 + lr] = v4.y * 0.125f;
            qT[(lc0 + 4*u + 2)*64 + lr] = v4.z * 0.125f;
            qT[(lc0 + 4*u + 3)*64 + lr] = v4.w * 0.125f;
        }
    }

    uint64_t accg[4][2], accl[4][2];
    #pragma unroll
    for (int i = 0; i < 4; i++) { accg[i][0]=0; accg[i][1]=0; accl[i][0]=0; accl[i][1]=0; }
    float mrow[4] = {-INFINITY, -INFINITY, -INFINITY, -INFINITY};
    float lg[4] = {0.f,0.f,0.f,0.f}, ll[4] = {0.f,0.f,0.f,0.f};

    const int qrow0 = qt*64 + ty*4;
    const int* lbase = lmask + ((size_t)b*S_ + qrow0) * S_;

    for (int kt = 0; kt < S_; kt += 64) {
        // ---- loads: kT (transposed), vs, ea ----
        {
            const float* kp = K + (size_t)(kt + lr)*64 + lc0;
            #pragma unroll
            for (int u = 0; u < 4; u++) {
                float4 v4 = *(const float4*)(kp + 4*u);
                kT[(lc0 + 4*u + 0)*64 + lr] = v4.x;
                kT[(lc0 + 4*u + 1)*64 + lr] = v4.y;
                kT[(lc0 + 4*u + 2)*64 + lr] = v4.z;
                kT[(lc0 + 4*u + 3)*64 + lr] = v4.w;
            }
            const float* vp = V + (size_t)(kt + lr)*64 + lc0;
            #pragma unroll
            for (int u = 0; u < 4; u++)
                *(float4*)&vs[lr*68 + lc0 + 4*u] = *(const float4*)(vp + 4*u);
        }
        if (tid < 64) ea[tid] = __expf(amask[b*S_ + kt + tid]);

        int4 lm[4];
        #pragma unroll
        for (int i = 0; i < 4; i++)
            lm[i] = *(const int4*)(lbase + (size_t)i*S_ + kt + tx*4);

        __syncthreads();

        // ---- scores (packed over q-row pairs) ----
        uint64_t sc2[2][4];
        #pragma unroll
        for (int j = 0; j < 4; j++) { sc2[0][j] = 0; sc2[1][j] = 0; }
        #pragma unroll 8
        for (int d = 0; d < 64; d++) {
            ulonglong2 q2 = *(const ulonglong2*)&qT[d*64 + ty*4];
            float4 k4 = *(const float4*)&kT[d*64 + tx*4];
            uint64_t kp0 = bpack(k4.x), kp1 = bpack(k4.y), kp2 = bpack(k4.z), kp3 = bpack(k4.w);
            fma2(sc2[0][0], q2.x, kp0); fma2(sc2[1][0], q2.y, kp0);
            fma2(sc2[0][1], q2.x, kp1); fma2(sc2[1][1], q2.y, kp1);
            fma2(sc2[0][2], q2.x, kp2); fma2(sc2[1][2], q2.y, kp2);
            fma2(sc2[0][3], q2.x, kp3); fma2(sc2[1][3], q2.y, kp3);
        }

        float s[4][4];
        #pragma unroll
        for (int p = 0; p < 2; p++)
            #pragma unroll
            for (int j = 0; j < 4; j++) {
                s[2*p  ][j] = lo32(sc2[p][j]);
                s[2*p+1][j] = hi32(sc2[p][j]);
            }

        float4 eaq = *(const float4*)&ea[tx*4];

        // ---- online softmax, fold ea/mask, store pg/pl ----
        #pragma unroll
        for (int i = 0; i < 4; i++) {
            float rmax = fmaxf(fmaxf(s[i][0], s[i][1]), fmaxf(s[i][2], s[i][3]));
            rmax = fmaxf(rmax, __shfl_xor_sync(0xffffffffu, rmax, 1));
            rmax = fmaxf(rmax, __shfl_xor_sync(0xffffffffu, rmax, 2));
            rmax = fmaxf(rmax, __shfl_xor_sync(0xffffffffu, rmax, 4));
            rmax = fmaxf(rmax, __shfl_xor_sync(0xffffffffu, rmax, 8));
            float nm = fmaxf(mrow[i], rmax);
            float corr = __expf(mrow[i] - nm);
            mrow[i] = nm;
            lg[i] *= corr; ll[i] *= corr;
            uint64_t c2 = bpack(corr);
            mul2(accg[i][0], c2); mul2(accg[i][1], c2);
            mul2(accl[i][0], c2); mul2(accl[i][1], c2);

            float pe0 = __expf(s[i][0] - nm);
            float pe1 = __expf(s[i][1] - nm);
            float pe2 = __expf(s[i][2] - nm);
            float pe3 = __expf(s[i][3] - nm);
            float pg0 = pe0 * eaq.x, pg1 = pe1 * eaq.y, pg2 = pe2 * eaq.z, pg3 = pe3 * eaq.w;
            float pl0 = lm[i].x ? pe0 : 0.f;
            float pl1 = lm[i].y ? pe1 : 0.f;
            float pl2 = lm[i].z ? pe2 : 0.f;
            float pl3 = lm[i].w ? pe3 : 0.f;

            float sg = (pg0 + pg1) + (pg2 + pg3);
            float sl = (pl0 + pl1) + (pl2 + pl3);
            sg += __shfl_xor_sync(0xffffffffu, sg, 1);
            sg += __shfl_xor_sync(0xffffffffu, sg, 2);
            sg += __shfl_xor_sync(0xffffffffu, sg, 4);
            sg += __shfl_xor_sync(0xffffffffu, sg, 8);
            sl += __shfl_xor_sync(0xffffffffu, sl, 1);
            sl += __shfl_xor_sync(0xffffffffu, sl, 2);
            sl += __shfl_xor_sync(0xffffffffu, sl, 4);
            sl += __shfl_xor_sync(0xffffffffu, sl, 8);
            lg[i] += sg; ll[i] += sl;

            *(float4*)&pg[(ty*4 + i)*68 + tx*4] = make_float4(pg0, pg1, pg2, pg3);
            *(float4*)&pl[(ty*4 + i)*68 + tx*4] = make_float4(pl0, pl1, pl2, pl3);
        }
        __syncthreads();

        // ---- PV: two FFMA2 streams (acc packed over d-pairs) ----
        #pragma unroll 2
        for (int cg = 0; cg < 16; cg++) {
            float pga[4][4], pla[4][4];
            #pragma unroll
            for (int i = 0; i < 4; i++) {
                float4 t = *(const float4*)&pg[(ty*4 + i)*68 + cg*4];
                pga[i][0]=t.x; pga[i][1]=t.y; pga[i][2]=t.z; pga[i][3]=t.w;
                float4 u = *(const float4*)&pl[(ty*4 + i)*68 + cg*4];
                pla[i][0]=u.x; pla[i][1]=u.y; pla[i][2]=u.z; pla[i][3]=u.w;
            }
            #pragma unroll
            for (int cc = 0; cc < 4; cc++) {
                ulonglong2 v2 = *(const ulonglong2*)&vs[(cg*4 + cc)*68 + tx*4];
                #pragma unroll
                for (int i = 0; i < 4; i++) {
                    uint64_t wg2 = bpack(pga[i][cc]);
                    uint64_t wl2 = bpack(pla[i][cc]);
                    fma2(accg[i][0], wg2, v2.x);
                    fma2(accg[i][1], wg2, v2.y);
                    fma2(accl[i][0], wl2, v2.x);
                    fma2(accl[i][1], wl2, v2.y);
                }
            }
        }
        __syncthreads();
    }

    // ---- gate + writeout ----
    #pragma unroll
    for (int i = 0; i < 4; i++) {
        const int row = qt*64 + ty*4 + i;
        const float g  = gate[((size_t)(b*NH_ + h))*S_ + row];
        const float il = g / ll[i];
        const float ig = (1.f - g) / lg[i];
        float4 o;
        o.x = lo32(accl[i][0])*il + lo32(accg[i][0])*ig;
        o.y = hi32(accl[i][0])*il + hi32(accg[i][0])*ig;
        o.z = lo32(accl[i][1])*il + lo32(accg[i][1])*ig;
        o.w = hi32(accl[i][1])*il + hi32(accg[i][1])*ig;
        *(float4*)&out[((size_t)(b*S_ + row))*H_ + h*DH_ + tx*4] = o;
    }
}

// ---------------------------------------------------------------------------
extern "C" void kernel_launch(void* const* d_in, const int* in_sizes, int n_in,
                              void* d_out, int out_size)
{
    const float* X     = (const float*)d_in[0];
    const float* amask = (const float*)d_in[1];
    const int*   lmask = (const int*)  d_in[2];
    const float* gate  = (const float*)d_in[3];
    const float* Wq    = (const float*)d_in[4];
    const float* bq    = (const float*)d_in[5];
    const float* Wk    = (const float*)d_in[6];
    const float* bk    = (const float*)d_in[7];
    const float* Wv    = (const float*)d_in[8];
    const float* bv    = (const float*)d_in[9];
    float* out = (float*)d_out;

    dim3 g1(H_/128, (B_*S_)/128, 3);
    qkv_gemm<<<g1, 256>>>(X, Wq, bq, Wk, bk, Wv, bv);

    cudaFuncSetAttribute(attn_kernel,
                         cudaFuncAttributeMaxDynamicSharedMemorySize,
                         SM_FLOATS * (int)sizeof(float));
    dim3 g2(NH_, S_/64, B_);
    attn_kernel<<<g2, 256, SM_FLOATS * sizeof(float)>>>(amask, lmask, gate, out);
}

// round 4
// speedup vs baseline: 4.2218x; 1.6915x over previous
#include <cuda_runtime.h>
#include <cuda_bf16.h>
#include <math.h>
#include <stdint.h>

// Inputs:
// 0 hidden_states f32 [2,2048,1024]
// 1 attention_mask f32 [2,1,1,2048]
// 2 local_attention_mask i32 [2,1,2048,2048]
// 3 gate_outputs f32 [2,16,2048,1]
// 4 Wq 5 bq 6 Wk 7 bk 8 Wv 9 bv
// out f32 [2,2048,1024]

#define B_  2
#define S_  2048
#define H_  1024
#define NH_ 16
#define DH_ 64

__device__ float g_q[B_*NH_*S_*DH_];
__device__ float g_k[B_*NH_*S_*DH_];
__device__ float g_v[B_*NH_*S_*DH_];

// ===================== helpers =====================
__device__ __forceinline__ uint32_t smem_u32(const void* p) {
    uint32_t a;
    asm("{ .reg .u64 t; cvta.to.shared.u64 t, %1; cvt.u32.u64 %0, t; }" : "=r"(a) : "l"(p));
    return a;
}
__device__ __forceinline__ float ex2f(float x) {
    float y; asm("ex2.approx.f32 %0, %1;" : "=f"(y) : "f"(x)); return y;
}
// pack two floats -> bf16x2 hi-part + bf16x2 residual
__device__ __forceinline__ void pack_split(float a, float b, uint32_t& hp, uint32_t& lp) {
    uint32_t h;
    asm("cvt.rn.bf16x2.f32 %0, %1, %2;" : "=r"(h) : "f"(b), "f"(a));
    float ah = __uint_as_float(h << 16);
    float bh = __uint_as_float(h & 0xffff0000u);
    float ar = a - ah, br = b - bh;
    uint32_t l;
    asm("cvt.rn.bf16x2.f32 %0, %1, %2;" : "=r"(l) : "f"(br), "f"(ar));
    hp = h; lp = l;
}
__device__ __forceinline__ void ldsm_x4(uint32_t* r, uint32_t a) {
    asm volatile("ldmatrix.sync.aligned.m8n8.x4.shared.b16 {%0,%1,%2,%3}, [%4];"
        : "=r"(r[0]), "=r"(r[1]), "=r"(r[2]), "=r"(r[3]) : "r"(a));
}
__device__ __forceinline__ void ldsm_x2(uint32_t* r, uint32_t a) {
    asm volatile("ldmatrix.sync.aligned.m8n8.x2.shared.b16 {%0,%1}, [%2];"
        : "=r"(r[0]), "=r"(r[1]) : "r"(a));
}
__device__ __forceinline__ void ldsm_x2t(uint32_t* r, uint32_t a) {
    asm volatile("ldmatrix.sync.aligned.m8n8.x2.trans.shared.b16 {%0,%1}, [%2];"
        : "=r"(r[0]), "=r"(r[1]) : "r"(a));
}
__device__ __forceinline__ void mma16816(float* c, const uint32_t* a, const uint32_t* b) {
    asm volatile("mma.sync.aligned.m16n8k16.row.col.f32.bf16.bf16.f32 "
        "{%0,%1,%2,%3}, {%4,%5,%6,%7}, {%8,%9}, {%0,%1,%2,%3};"
        : "+f"(c[0]), "+f"(c[1]), "+f"(c[2]), "+f"(c[3])
        : "r"(a[0]), "r"(a[1]), "r"(a[2]), "r"(a[3]), "r"(b[0]), "r"(b[1]));
}

// ---------------- f32x2 packed helpers (QKV SIMT path) ----------------
__device__ __forceinline__ uint64_t bpack(float x) {
    uint64_t r;
    asm("mov.b64 %0, {%1, %1};" : "=l"(r) : "r"(__float_as_uint(x)));
    return r;
}
__device__ __forceinline__ void fma2(uint64_t& d, uint64_t a, uint64_t b) {
    asm("fma.rn.f32x2 %0, %1, %2, %0;" : "+l"(d) : "l"(a), "l"(b));
}
__device__ __forceinline__ float lo32(uint64_t v) { return __uint_as_float((uint32_t)v); }
__device__ __forceinline__ float hi32(uint64_t v) { return __uint_as_float((uint32_t)(v >> 32)); }

// ---------------------------------------------------------------------------
// QKV projection (R2, unchanged): 128x128x8 tiles, FFMA2.
// ---------------------------------------------------------------------------
__global__ __launch_bounds__(256, 2) void qkv_gemm(
    const float* __restrict__ X,
    const float* __restrict__ Wq, const float* __restrict__ bq,
    const float* __restrict__ Wk, const float* __restrict__ bk,
    const float* __restrict__ Wv, const float* __restrict__ bv)
{
    __shared__ float As[8 * 132];
    __shared__ float Bs[8 * 132];

    const int z = blockIdx.z;
    const float* __restrict__ W    = (z == 0) ? Wq : (z == 1) ? Wk : Wv;
    const float* __restrict__ bias = (z == 0) ? bq : (z == 1) ? bk : bv;
    float* __restrict__ outp       = (z == 0) ? g_q : (z == 1) ? g_k : g_v;

    const int m0 = blockIdx.y * 128;
    const int n0 = blockIdx.x * 128;
    const int tid = threadIdx.x;
    const int tx = tid & 15;
    const int ty = tid >> 4;
    const int lrow = tid >> 1;
    const int lk4  = (tid & 1) * 4;

    const float* ap = X + (size_t)(m0 + lrow) * H_ + lk4;
    const float* bp = W + (size_t)(n0 + lrow) * H_ + lk4;

    float4 pa = *(const float4*)ap;
    float4 pb = *(const float4*)bp;

    uint64_t acc[8][4];
    #pragma unroll
    for (int i = 0; i < 8; i++)
        #pragma unroll
        for (int j = 0; j < 4; j++) acc[i][j] = 0ull;

    for (int k0 = 0; k0 < H_; k0 += 8) {
        __syncthreads();
        As[(lk4+0)*132 + lrow] = pa.x; As[(lk4+1)*132 + lrow] = pa.y;
        As[(lk4+2)*132 + lrow] = pa.z; As[(lk4+3)*132 + lrow] = pa.w;
        Bs[(lk4+0)*132 + lrow] = pb.x; Bs[(lk4+1)*132 + lrow] = pb.y;
        Bs[(lk4+2)*132 + lrow] = pb.z; Bs[(lk4+3)*132 + lrow] = pb.w;
        if (k0 + 8 < H_) {
            pa = *(const float4*)(ap + k0 + 8);
            pb = *(const float4*)(bp + k0 + 8);
        }
        __syncthreads();

        #pragma unroll
        for (int k = 0; k < 8; k++) {
            ulonglong2 b01 = *(const ulonglong2*)&Bs[k*132 + tx*4];
            ulonglong2 b23 = *(const ulonglong2*)&Bs[k*132 + 64 + tx*4];
            float4 a03 = *(const float4*)&As[k*132 + ty*4];
            float4 a47 = *(const float4*)&As[k*132 + 64 + ty*4];
            float am[8] = {a03.x, a03.y, a03.z, a03.w, a47.x, a47.y, a47.z, a47.w};
            #pragma unroll
            for (int i = 0; i < 8; i++) {
                uint64_t a2 = bpack(am[i]);
                fma2(acc[i][0], a2, b01.x);
                fma2(acc[i][1], a2, b01.y);
                fma2(acc[i][2], a2, b23.x);
                fma2(acc[i][3], a2, b23.y);
            }
        }
    }

    const int h0 = n0 >> 6;
    float4 bias0 = *(const float4*)&bias[n0 + tx*4];
    float4 bias1 = *(const float4*)&bias[n0 + 64 + tx*4];
    #pragma unroll
    for (int i = 0; i < 8; i++) {
        const int m  = m0 + ((i < 4) ? (ty*4 + i) : (64 + ty*4 + i - 4));
        const int bI = m >> 11;
        const int s  = m & (S_ - 1);
        float4 o0, o1;
        o0.x = lo32(acc[i][0]) + bias0.x; o0.y = hi32(acc[i][0]) + bias0.y;
        o0.z = lo32(acc[i][1]) + bias0.z; o0.w = hi32(acc[i][1]) + bias0.w;
        o1.x = lo32(acc[i][2]) + bias1.x; o1.y = hi32(acc[i][2]) + bias1.y;
        o1.z = lo32(acc[i][3]) + bias1.z; o1.w = hi32(acc[i][3]) + bias1.w;
        *(float4*)&outp[(((size_t)(bI*NH_ + h0  ))*S_ + s)*DH_ + tx*4] = o0;
        *(float4*)&outp[(((size_t)(bI*NH_ + h0+1))*S_ + s)*DH_ + tx*4] = o1;
    }
}

// ---------------------------------------------------------------------------
// mma.sync bf16 dual-branch flash attention (split precision, no online max).
// Block = (h, q-tile of 128, b), 256 threads = 8 warps; warp w owns rows w*16..+15.
// Scores: Sh = Qh Kh^T + Qh Kl^T + Ql Kh^T  (error ~2^-18)
// Softmax: p = 2^s (Q pre-scaled by log2e/8); pg = p*ea; pl = mask? p:0.
// PV:  ctx += (Ph Vh + Ph Vl + Pl Vh) per branch, fp32 register accumulators
//      across all k-tiles (no rescale). Score C-frags repacked in registers
//      directly to PV A-frags.
// ---------------------------------------------------------------------------
#define EA_OFF 0
#define QH_OFF 8192
#define QL_OFF 26624
#define KH_OFF 45056
#define KL_OFF 54272
#define VH_OFF 63488
#define VL_OFF 72704
#define SM_BYTES 81920
#define RSTRIDE 144          // 72 bf16 per row

__global__ __launch_bounds__(256) void attn_mma(
    const float* __restrict__ amask, const int* __restrict__ lmask,
    const float* __restrict__ gate,  float* __restrict__ out)
{
    extern __shared__ char smem[];
    const uint32_t sb = smem_u32(smem);
    float* ea_s = (float*)smem;

    const int tid  = threadIdx.x;
    const int lane = tid & 31;
    const int h  = blockIdx.x;
    const int qt = blockIdx.y;
    const int b  = blockIdx.z;
    const size_t base = ((size_t)(b*NH_ + h)) * S_ * DH_;

    // ---- ea = exp(amask) ----
    #pragma unroll
    for (int i = 0; i < 8; i++)
        ea_s[tid + 256*i] = __expf(amask[b*S_ + tid + 256*i]);

    // ---- Q -> bf16 split smem, scaled by log2e/sqrt(DH) ----
    {
        const float SCALE = 0.18033688011112042f;   // 0.125 * log2(e)
        const int qr = tid >> 1;
        const int dq = (tid & 1) * 32;
        const float* qp = g_q + base + (size_t)(qt*128 + qr)*DH_ + dq;
        const uint32_t rowoff = (uint32_t)(qr*RSTRIDE + dq*2);
        #pragma unroll
        for (int u = 0; u < 8; u++) {
            float4 f = *(const float4*)(qp + 4*u);
            f.x *= SCALE; f.y *= SCALE; f.z *= SCALE; f.w *= SCALE;
            uint32_t h0, l0, h1, l1;
            pack_split(f.x, f.y, h0, l0);
            pack_split(f.z, f.w, h1, l1);
            *(uint32_t*)(smem + QH_OFF + rowoff + u*8)     = h0;
            *(uint32_t*)(smem + QH_OFF + rowoff + u*8 + 4) = h1;
            *(uint32_t*)(smem + QL_OFF + rowoff + u*8)     = l0;
            *(uint32_t*)(smem + QL_OFF + rowoff + u*8 + 4) = l1;
        }
    }
    __syncthreads();

    // per-thread fragment coordinates
    const int qr0 = (tid >> 5) * 16;                 // warp row base
    const int qrowLo = qt*128 + qr0 + (lane >> 2);   // C-frag rows
    const int* mLo = lmask + ((size_t)b*S_ + qrowLo)*S_ + (lane & 3)*2;
    const int* mHi = mLo + 8*S_;

    float cg[8][4], cl[8][4];
    #pragma unroll
    for (int nb = 0; nb < 8; nb++)
        #pragma unroll
        for (int e = 0; e < 4; e++) { cg[nb][e] = 0.f; cl[nb][e] = 0.f; }
    float lg0 = 0.f, lg1 = 0.f, ll0 = 0.f, ll1 = 0.f;

    // K/V conversion slot for this thread
    const int kr = tid >> 2;
    const int dq = (tid & 3) * 16;
    const uint32_t kvoff = (uint32_t)(kr*RSTRIDE + dq*2);

    for (int kt = 0; kt < S_; kt += 64) {
        if (kt) __syncthreads();   // previous tile's mma reads done

        // ---- convert K, V tiles to bf16 splits ----
        {
            const float* kp = g_k + base + (size_t)(kt + kr)*DH_ + dq;
            const float* vp = g_v + base + (size_t)(kt + kr)*DH_ + dq;
            #pragma unroll
            for (int u = 0; u < 4; u++) {
                float4 f = *(const float4*)(kp + 4*u);
                uint32_t h0, l0, h1, l1;
                pack_split(f.x, f.y, h0, l0);
                pack_split(f.z, f.w, h1, l1);
                *(uint32_t*)(smem + KH_OFF + kvoff + u*8)     = h0;
                *(uint32_t*)(smem + KH_OFF + kvoff + u*8 + 4) = h1;
                *(uint32_t*)(smem + KL_OFF + kvoff + u*8)     = l0;
                *(uint32_t*)(smem + KL_OFF + kvoff + u*8 + 4) = l1;
                float4 g = *(const float4*)(vp + 4*u);
                pack_split(g.x, g.y, h0, l0);
                pack_split(g.z, g.w, h1, l1);
                *(uint32_t*)(smem + VH_OFF + kvoff + u*8)     = h0;
                *(uint32_t*)(smem + VH_OFF + kvoff + u*8 + 4) = h1;
                *(uint32_t*)(smem + VL_OFF + kvoff + u*8)     = l0;
                *(uint32_t*)(smem + VL_OFF + kvoff + u*8 + 4) = l1;
            }
        }
        __syncthreads();

        // ---- prefetch local-mask bits for this tile ----
        int2 mkLo[8], mkHi[8];
        #pragma unroll
        for (int nb = 0; nb < 8; nb++) {
            mkLo[nb] = *(const int2*)&mLo[kt + nb*8];
            mkHi[nb] = *(const int2*)&mHi[kt + nb*8];
        }

        // ---- QK^T: 3-pass split ----
        float p[8][4];
        #pragma unroll
        for (int nb = 0; nb < 8; nb++)
            #pragma unroll
            for (int e = 0; e < 4; e++) p[nb][e] = 0.f;

        const int la = lane & 15;
        #pragma unroll
        for (int kb = 0; kb < 4; kb++) {
            uint32_t aqh[4], aql[4];
            const uint32_t qaddr = (uint32_t)((qr0 + la)*RSTRIDE + kb*32 + (lane >> 4)*16);
            ldsm_x4(aqh, sb + QH_OFF + qaddr);
            ldsm_x4(aql, sb + QL_OFF + qaddr);
            #pragma unroll
            for (int nb = 0; nb < 8; nb++) {
                uint32_t bh[2], bl[2];
                const uint32_t kaddr = (uint32_t)((nb*8 + (la & 7))*RSTRIDE + kb*32 + (la >> 3)*16);
                ldsm_x2(bh, sb + KH_OFF + kaddr);
                ldsm_x2(bl, sb + KL_OFF + kaddr);
                mma16816(p[nb], aqh, bh);
                mma16816(p[nb], aqh, bl);
                mma16816(p[nb], aql, bh);
            }
        }

        // ---- softmax + fragment repack ----
        uint32_t apgh[4][4], apgl[4][4], aplh[4][4], apll[4][4];
        #pragma unroll
        for (int nb = 0; nb < 8; nb++) {
            const int col = kt + nb*8 + (lane & 3)*2;
            float2 ee = *(const float2*)&ea_s[col];
            float e0 = ex2f(p[nb][0]);
            float e1 = ex2f(p[nb][1]);
            float e2 = ex2f(p[nb][2]);
            float e3 = ex2f(p[nb][3]);
            float g0 = e0*ee.x, g1 = e1*ee.y, g2 = e2*ee.x, g3 = e3*ee.y;
            float l0 = mkLo[nb].x ? e0 : 0.f;
            float l1 = mkLo[nb].y ? e1 : 0.f;
            float l2 = mkHi[nb].x ? e2 : 0.f;
            float l3 = mkHi[nb].y ? e3 : 0.f;
            lg0 += g0 + g1; lg1 += g2 + g3;
            ll0 += l0 + l1; ll1 += l2 + l3;
            const int kb = nb >> 1, hf = (nb & 1) * 2;
            pack_split(g0, g1, apgh[kb][hf+0], apgl[kb][hf+0]);
            pack_split(g2, g3, apgh[kb][hf+1], apgl[kb][hf+1]);
            pack_split(l0, l1, aplh[kb][hf+0], apll[kb][hf+0]);
            pack_split(l2, l3, aplh[kb][hf+1], apll[kb][hf+1]);
        }

        // ---- PV: 3-pass split, both branches ----
        #pragma unroll
        for (int kb = 0; kb < 4; kb++) {
            #pragma unroll
            for (int nb = 0; nb < 8; nb++) {
                uint32_t bvh[2], bvl[2];
                const uint32_t vaddr = (uint32_t)((kb*16 + la)*RSTRIDE + nb*16);
                ldsm_x2t(bvh, sb + VH_OFF + vaddr);
                ldsm_x2t(bvl, sb + VL_OFF + vaddr);
                mma16816(cg[nb], apgh[kb], bvh);
                mma16816(cg[nb], apgh[kb], bvl);
                mma16816(cg[nb], apgl[kb], bvh);
                mma16816(cl[nb], aplh[kb], bvh);
                mma16816(cl[nb], aplh[kb], bvl);
                mma16816(cl[nb], apll[kb], bvh);
            }
        }
    }

    // ---- row-sum reduction across quad ----
    lg0 += __shfl_xor_sync(0xffffffffu, lg0, 1); lg0 += __shfl_xor_sync(0xffffffffu, lg0, 2);
    lg1 += __shfl_xor_sync(0xffffffffu, lg1, 1); lg1 += __shfl_xor_sync(0xffffffffu, lg1, 2);
    ll0 += __shfl_xor_sync(0xffffffffu, ll0, 1); ll0 += __shfl_xor_sync(0xffffffffu, ll0, 2);
    ll1 += __shfl_xor_sync(0xffffffffu, ll1, 1); ll1 += __shfl_xor_sync(0xffffffffu, ll1, 2);

    // ---- gate + writeout ----
    const float gLo = gate[((size_t)(b*NH_ + h))*S_ + qrowLo];
    const float gHi = gate[((size_t)(b*NH_ + h))*S_ + qrowLo + 8];
    const float igLo = (1.f - gLo) / lg0, ilLo = gLo / ll0;
    const float igHi = (1.f - gHi) / lg1, ilHi = gHi / ll1;
    float* oLo = out + ((size_t)(b*S_ + qrowLo))*H_ + h*DH_ + (lane & 3)*2;
    float* oHi = oLo + 8*H_;
    #pragma unroll
    for (int nb = 0; nb < 8; nb++) {
        float2 a, c2;
        a.x  = cl[nb][0]*ilLo + cg[nb][0]*igLo;
        a.y  = cl[nb][1]*ilLo + cg[nb][1]*igLo;
        c2.x = cl[nb][2]*ilHi + cg[nb][2]*igHi;
        c2.y = cl[nb][3]*ilHi + cg[nb][3]*igHi;
        *(float2*)(oLo + nb*8) = a;
        *(float2*)(oHi + nb*8) = c2;
    }
}

// ---------------------------------------------------------------------------
extern "C" void kernel_launch(void* const* d_in, const int* in_sizes, int n_in,
                              void* d_out, int out_size)
{
    const float* X     = (const float*)d_in[0];
    const float* amask = (const float*)d_in[1];
    const int*   lmask = (const int*)  d_in[2];
    const float* gate  = (const float*)d_in[3];
    const float* Wq    = (const float*)d_in[4];
    const float* bq    = (const float*)d_in[5];
    const float* Wk    = (const float*)d_in[6];
    const float* bk    = (const float*)d_in[7];
    const float* Wv    = (const float*)d_in[8];
    const float* bv    = (const float*)d_in[9];
    float* out = (float*)d_out;

    dim3 g1(H_/128, (B_*S_)/128, 3);
    qkv_gemm<<<g1, 256>>>(X, Wq, bq, Wk, bk, Wv, bv);

    cudaFuncSetAttribute(attn_mma, cudaFuncAttributeMaxDynamicSharedMemorySize, SM_BYTES);
    dim3 g2(NH_, S_/128, B_);   // heads fastest -> lmask rows shared in L2
    attn_mma<<<g2, 256, SM_BYTES>>>(amask, lmask, gate, out);
}

// round 5
// speedup vs baseline: 5.9619x; 1.4122x over previous
#include <cuda_runtime.h>
#include <cuda_bf16.h>
#include <math.h>
#include <stdint.h>

// Inputs:
// 0 hidden_states f32 [2,2048,1024]
// 1 attention_mask f32 [2,1,1,2048]
// 2 local_attention_mask i32 [2,1,2048,2048]
// 3 gate_outputs f32 [2,16,2048,1]
// 4 Wq 5 bq 6 Wk 7 bk 8 Wv 9 bv
// out f32 [2,2048,1024]

#define B_  2
#define S_  2048
#define H_  1024
#define NH_ 16
#define DH_ 64
#define SCALE_Q 0.18033688011112042f   // 0.125 * log2(e)

// bf16 split scratch (device globals; no allocation allowed)
__device__ __nv_bfloat16 g_xh[(size_t)B_*S_*H_], g_xl[(size_t)B_*S_*H_];
__device__ __nv_bfloat16 g_wh[3][(size_t)H_*H_], g_wl[3][(size_t)H_*H_];
__device__ __nv_bfloat16 g_qh[(size_t)B_*NH_*S_*DH_], g_ql[(size_t)B_*NH_*S_*DH_];
__device__ __nv_bfloat16 g_kh[(size_t)B_*NH_*S_*DH_], g_kl[(size_t)B_*NH_*S_*DH_];
__device__ __nv_bfloat16 g_vh[(size_t)B_*NH_*S_*DH_], g_vl[(size_t)B_*NH_*S_*DH_];

// ===================== helpers =====================
__device__ __forceinline__ uint32_t smem_u32(const void* p) {
    uint32_t a;
    asm("{ .reg .u64 t; cvta.to.shared.u64 t, %1; cvt.u32.u64 %0, t; }" : "=r"(a) : "l"(p));
    return a;
}
__device__ __forceinline__ float ex2f(float x) {
    float y; asm("ex2.approx.f32 %0, %1;" : "=f"(y) : "f"(x)); return y;
}
__device__ __forceinline__ void pack_split(float a, float b, uint32_t& hp, uint32_t& lp) {
    uint32_t h;
    asm("cvt.rn.bf16x2.f32 %0, %1, %2;" : "=r"(h) : "f"(b), "f"(a));
    float ah = __uint_as_float(h << 16);
    float bh = __uint_as_float(h & 0xffff0000u);
    float ar = a - ah, br = b - bh;
    uint32_t l;
    asm("cvt.rn.bf16x2.f32 %0, %1, %2;" : "=r"(l) : "f"(br), "f"(ar));
    hp = h; lp = l;
}
__device__ __forceinline__ void ldsm_x4(uint32_t* r, uint32_t a) {
    asm volatile("ldmatrix.sync.aligned.m8n8.x4.shared.b16 {%0,%1,%2,%3}, [%4];"
        : "=r"(r[0]), "=r"(r[1]), "=r"(r[2]), "=r"(r[3]) : "r"(a));
}
__device__ __forceinline__ void ldsm_x2(uint32_t* r, uint32_t a) {
    asm volatile("ldmatrix.sync.aligned.m8n8.x2.shared.b16 {%0,%1}, [%2];"
        : "=r"(r[0]), "=r"(r[1]) : "r"(a));
}
__device__ __forceinline__ void ldsm_x2t(uint32_t* r, uint32_t a) {
    asm volatile("ldmatrix.sync.aligned.m8n8.x2.trans.shared.b16 {%0,%1}, [%2];"
        : "=r"(r[0]), "=r"(r[1]) : "r"(a));
}
__device__ __forceinline__ void mma16816(float* c, const uint32_t* a, const uint32_t* b) {
    asm volatile("mma.sync.aligned.m16n8k16.row.col.f32.bf16.bf16.f32 "
        "{%0,%1,%2,%3}, {%4,%5,%6,%7}, {%8,%9}, {%0,%1,%2,%3};"
        : "+f"(c[0]), "+f"(c[1]), "+f"(c[2]), "+f"(c[3])
        : "r"(a[0]), "r"(a[1]), "r"(a[2]), "r"(a[3]), "r"(b[0]), "r"(b[1]));
}
#define CPASYNC(dst, src) \
    asm volatile("cp.async.cg.shared.global [%0], [%1], 16;" :: "r"(dst), "l"(src))
#define CPCOMMIT() asm volatile("cp.async.commit_group;" ::: "memory")
#define CPWAIT(n)  asm volatile("cp.async.wait_group %0;" :: "n"(n) : "memory")

// ---------------------------------------------------------------------------
// fp32 -> bf16 split converter.  which: 0=X, 1..3=Wq/Wk/Wv
// ---------------------------------------------------------------------------
__global__ __launch_bounds__(256) void cvt_split(const float4* __restrict__ src, int which, int n4)
{
    int i = blockIdx.x * 256 + threadIdx.x;
    if (i >= n4) return;
    uint2* dh;
    uint2* dl;
    if (which == 0)      { dh = (uint2*)g_xh;    dl = (uint2*)g_xl;    }
    else                 { dh = (uint2*)g_wh[which-1]; dl = (uint2*)g_wl[which-1]; }
    float4 f = src[i];
    uint32_t h0, l0, h1, l1;
    pack_split(f.x, f.y, h0, l0);
    pack_split(f.z, f.w, h1, l1);
    dh[i] = make_uint2(h0, h1);
    dl[i] = make_uint2(l0, l1);
}

// ---------------------------------------------------------------------------
// QKV projection via split-bf16 HMMA:  out = X @ W^T + b -> bf16 h/l split,
// [B,NH,S,DH] layout; Q additionally scaled by log2e/8.
// BM=128, BN=128, BK=32; 8 warps (2m x 4n), warp tile 64x32; double-buffered
// cp.async smem; 3-pass error compensation (AhBh + AhBl + AlBh).
// ---------------------------------------------------------------------------
#define GS 80                 // smem row stride bytes (32 bf16 = 64 B + 16 pad)
#define GXH(buf) ((buf)*40960 + 0)
#define GXL(buf) ((buf)*40960 + 10240)
#define GWH(buf) ((buf)*40960 + 20480)
#define GWL(buf) ((buf)*40960 + 30720)
#define G_SMEM  81920

__global__ __launch_bounds__(256) void qkv_hmma(
    const float* __restrict__ bq, const float* __restrict__ bk_,
    const float* __restrict__ bv)
{
    extern __shared__ char smem[];
    const uint32_t sb = smem_u32(smem);
    const int tid  = threadIdx.x;
    const int lane = tid & 31;
    const int wid  = tid >> 5;
    const int wm   = wid >> 2;        // 0..1
    const int wn   = wid & 3;         // 0..3
    const int z    = blockIdx.z;
    const int m0   = blockIdx.y * 128;
    const int n0   = blockIdx.x * 128;

    const __nv_bfloat16* xh = g_xh;
    const __nv_bfloat16* xl = g_xl;
    const __nv_bfloat16* wh = g_wh[z];
    const __nv_bfloat16* wl = g_wl[z];
    const float* bias = (z == 0) ? bq : (z == 1) ? bk_ : bv;
    __nv_bfloat16* oh = (z == 0) ? g_qh : (z == 1) ? g_kh : g_vh;
    __nv_bfloat16* ol = (z == 0) ? g_ql : (z == 1) ? g_ql : g_vl; // fixed below
    if (z == 1) ol = g_kl;

    // ---- async tile copy: 4 arrays x 512 chunks(16B), 2 chunks/thread/arr ----
    auto issue_copy = [&](int buf, int k0) {
        #pragma unroll
        for (int u = 0; u < 2; u++) {
            const int chunk = tid*2 + u;       // 0..511
            const int row = chunk >> 2, c16 = chunk & 3;
            const uint32_t so = (uint32_t)(row*GS + c16*16);
            CPASYNC(sb + GXH(buf) + so, (const char*)(xh + (size_t)(m0+row)*H_ + k0 + c16*8));
            CPASYNC(sb + GXL(buf) + so, (const char*)(xl + (size_t)(m0+row)*H_ + k0 + c16*8));
            CPASYNC(sb + GWH(buf) + so, (const char*)(wh + (size_t)(n0+row)*H_ + k0 + c16*8));
            CPASYNC(sb + GWL(buf) + so, (const char*)(wl + (size_t)(n0+row)*H_ + k0 + c16*8));
        }
        CPCOMMIT();
    };

    float c[4][4][4];
    #pragma unroll
    for (int mi = 0; mi < 4; mi++)
        #pragma unroll
        for (int ni = 0; ni < 4; ni++)
            #pragma unroll
            for (int e = 0; e < 4; e++) c[mi][ni][e] = 0.f;

    issue_copy(0, 0);

    const int la = lane & 15;
    const int NSTEP = H_ / 32;                 // 32
    for (int t = 0; t < NSTEP; t++) {
        __syncthreads();
        if (t + 1 < NSTEP) { issue_copy((t+1)&1, (t+1)*32); CPWAIT(1); }
        else               { CPWAIT(0); }
        __syncthreads();

        const uint32_t xh_b = sb + GXH(t&1), xl_b = sb + GXL(t&1);
        const uint32_t wh_b = sb + GWH(t&1), wl_b = sb + GWL(t&1);
        #pragma unroll
        for (int kk = 0; kk < 2; kk++) {
            uint32_t Ah[4][4], Al[4][4], Bh[4][2], Bl[4][2];
            #pragma unroll
            for (int mi = 0; mi < 4; mi++) {
                const uint32_t ao = (uint32_t)((wm*64 + mi*16 + la)*GS + kk*32 + (lane>>4)*16);
                ldsm_x4(Ah[mi], xh_b + ao);
                ldsm_x4(Al[mi], xl_b + ao);
            }
            #pragma unroll
            for (int ni = 0; ni < 4; ni++) {
                const uint32_t bo = (uint32_t)((wn*32 + ni*8 + (la & 7))*GS + kk*32 + (la>>3)*16);
                ldsm_x2(Bh[ni], wh_b + bo);
                ldsm_x2(Bl[ni], wl_b + bo);
            }
            #pragma unroll
            for (int mi = 0; mi < 4; mi++)
                #pragma unroll
                for (int ni = 0; ni < 4; ni++) {
                    mma16816(c[mi][ni], Ah[mi], Bh[ni]);
                    mma16816(c[mi][ni], Ah[mi], Bl[ni]);
                    mma16816(c[mi][ni], Al[mi], Bh[ni]);
                }
        }
    }

    // ---- epilogue: +bias, (scale if Q), split to bf16 h/l, [B,NH,S,DH] ----
    const float sc = (z == 0) ? SCALE_Q : 1.f;
    #pragma unroll
    for (int ni = 0; ni < 4; ni++) {
        const int nb_ = n0 + wn*32 + ni*8 + (lane & 3)*2;
        const float b0 = bias[nb_], b1 = bias[nb_ + 1];
        const int hh = nb_ >> 6, d = nb_ & 63;
        #pragma unroll
        for (int mi = 0; mi < 4; mi++) {
            #pragma unroll
            for (int half = 0; half < 2; half++) {
                const int r = m0 + wm*64 + mi*16 + (lane >> 2) + half*8;
                const int bI = r >> 11, s = r & (S_ - 1);
                float v0 = (c[mi][ni][half*2 + 0] + b0) * sc;
                float v1 = (c[mi][ni][half*2 + 1] + b1) * sc;
                uint32_t hp, lp;
                pack_split(v0, v1, hp, lp);
                const size_t pidx = ((((size_t)bI*NH_ + hh)*S_ + s)*DH_ + d) >> 1;
                ((uint32_t*)oh)[pidx] = hp;
                ((uint32_t*)ol)[pidx] = lp;
            }
        }
    }
}

// ---------------------------------------------------------------------------
// mma.sync bf16 dual-branch flash attention (split precision, no online max).
// Q/K/V arrive pre-split in bf16 (Q pre-scaled). K/V tiles double-buffered
// via cp.async. Per warp: 16 q-rows; fp32 ctx accumulators across all tiles.
// ---------------------------------------------------------------------------
#define EA_OFF 0
#define QH_OFF 8192
#define QL_OFF 26624
#define KV_OFF 45056
#define KVB    36864          // per-buffer span
#define KH_O   0
#define KL_O   9216
#define VH_O   18432
#define VL_O   27648
#define SM_BYTES 118784
#define RSTRIDE 144           // 64 bf16 = 128 B + 16 pad

__global__ __launch_bounds__(256) void attn_mma(
    const float* __restrict__ amask, const int* __restrict__ lmask,
    const float* __restrict__ gate,  float* __restrict__ out)
{
    extern __shared__ char smem[];
    const uint32_t sb = smem_u32(smem);
    float* ea_s = (float*)smem;

    const int tid  = threadIdx.x;
    const int lane = tid & 31;
    const int h  = blockIdx.x;
    const int qt = blockIdx.y;
    const int b  = blockIdx.z;
    const size_t base = ((size_t)(b*NH_ + h)) * S_ * DH_;

    // ---- ea = exp(amask) ----
    #pragma unroll
    for (int i = 0; i < 8; i++)
        ea_s[tid + 256*i] = __expf(amask[b*S_ + tid + 256*i]);

    // ---- Q h/l tiles -> smem (plain copies; already scaled) ----
    #pragma unroll
    for (int u = 0; u < 8; u++) {
        const int idx = tid*8 + u;             // 0..2047
        const int arr = idx >> 10;             // 0: qh, 1: ql
        const int rem = idx & 1023;
        const int row = rem >> 3, c16 = rem & 7;
        const __nv_bfloat16* src = (arr ? g_ql : g_qh) + base + (size_t)(qt*128 + row)*DH_ + c16*8;
        uint4 v = *(const uint4*)src;
        *(uint4*)(smem + (arr ? QL_OFF : QH_OFF) + row*RSTRIDE + c16*16) = v;
    }

    // ---- K/V async copy machinery ----
    auto issue_kv = [&](int buf, int kt) {
        const uint32_t bb = sb + KV_OFF + buf*KVB;
        #pragma unroll
        for (int u = 0; u < 2; u++) {
            const int chunk = tid*2 + u;       // 0..511
            const int row = chunk >> 3, c16 = chunk & 7;
            const uint32_t so = (uint32_t)(row*RSTRIDE + c16*16);
            const size_t go = base + (size_t)(kt + row)*DH_ + c16*8;
            CPASYNC(bb + KH_O + so, (const char*)(g_kh + go));
            CPASYNC(bb + KL_O + so, (const char*)(g_kl + go));
            CPASYNC(bb + VH_O + so, (const char*)(g_vh + go));
            CPASYNC(bb + VL_O + so, (const char*)(g_vl + go));
        }
        CPCOMMIT();
    };

    // per-thread fragment coordinates
    const int qr0 = (tid >> 5) * 16;
    const int qrowLo = qt*128 + qr0 + (lane >> 2);
    const int* mLo = lmask + ((size_t)b*S_ + qrowLo)*S_ + (lane & 3)*2;
    const int* mHi = mLo + 8*S_;

    float cg[8][4], cl[8][4];
    #pragma unroll
    for (int nb = 0; nb < 8; nb++)
        #pragma unroll
        for (int e = 0; e < 4; e++) { cg[nb][e] = 0.f; cl[nb][e] = 0.f; }
    float lg0 = 0.f, lg1 = 0.f, ll0 = 0.f, ll1 = 0.f;

    issue_kv(0, 0);

    const int la = lane & 15;
    const int NT = S_ / 64;                    // 32
    for (int t = 0; t < NT; t++) {
        const int kt = t * 64;
        __syncthreads();                       // buf (t+1)&1 readers (iter t-1) done
        if (t + 1 < NT) { issue_kv((t+1)&1, kt + 64); CPWAIT(1); }
        else            { CPWAIT(0); }
        __syncthreads();

        const uint32_t kh_b = sb + KV_OFF + (t&1)*KVB + KH_O;
        const uint32_t kl_b = sb + KV_OFF + (t&1)*KVB + KL_O;
        const uint32_t vh_b = sb + KV_OFF + (t&1)*KVB + VH_O;
        const uint32_t vl_b = sb + KV_OFF + (t&1)*KVB + VL_O;

        // ---- prefetch local-mask bits ----
        int2 mkLo[8], mkHi[8];
        #pragma unroll
        for (int nb = 0; nb < 8; nb++) {
            mkLo[nb] = *(const int2*)&mLo[kt + nb*8];
            mkHi[nb] = *(const int2*)&mHi[kt + nb*8];
        }

        // ---- QK^T: 3-pass split ----
        float p[8][4];
        #pragma unroll
        for (int nb = 0; nb < 8; nb++)
            #pragma unroll
            for (int e = 0; e < 4; e++) p[nb][e] = 0.f;

        #pragma unroll
        for (int kb = 0; kb < 4; kb++) {
            uint32_t aqh[4], aql[4];
            const uint32_t qaddr = (uint32_t)((qr0 + la)*RSTRIDE + kb*32 + (lane >> 4)*16);
            ldsm_x4(aqh, sb + QH_OFF + qaddr);
            ldsm_x4(aql, sb + QL_OFF + qaddr);
            #pragma unroll
            for (int nb = 0; nb < 8; nb++) {
                uint32_t bh[2], bl[2];
                const uint32_t kaddr = (uint32_t)((nb*8 + (la & 7))*RSTRIDE + kb*32 + (la >> 3)*16);
                ldsm_x2(bh, kh_b + kaddr);
                ldsm_x2(bl, kl_b + kaddr);
                mma16816(p[nb], aqh, bh);
                mma16816(p[nb], aqh, bl);
                mma16816(p[nb], aql, bh);
            }
        }

        // ---- softmax + fragment repack ----
        uint32_t apgh[4][4], apgl[4][4], aplh[4][4], apll[4][4];
        #pragma unroll
        for (int nb = 0; nb < 8; nb++) {
            const int col = kt + nb*8 + (lane & 3)*2;
            float2 ee = *(const float2*)&ea_s[col];
            float e0 = ex2f(p[nb][0]);
            float e1 = ex2f(p[nb][1]);
            float e2 = ex2f(p[nb][2]);
            float e3 = ex2f(p[nb][3]);
            float g0 = e0*ee.x, g1 = e1*ee.y, g2 = e2*ee.x, g3 = e3*ee.y;
            float l0 = mkLo[nb].x ? e0 : 0.f;
            float l1 = mkLo[nb].y ? e1 : 0.f;
            float l2 = mkHi[nb].x ? e2 : 0.f;
            float l3 = mkHi[nb].y ? e3 : 0.f;
            lg0 += g0 + g1; lg1 += g2 + g3;
            ll0 += l0 + l1; ll1 += l2 + l3;
            const int kb = nb >> 1, hf = (nb & 1) * 2;
            pack_split(g0, g1, apgh[kb][hf+0], apgl[kb][hf+0]);
            pack_split(g2, g3, apgh[kb][hf+1], apgl[kb][hf+1]);
            pack_split(l0, l1, aplh[kb][hf+0], apll[kb][hf+0]);
            pack_split(l2, l3, aplh[kb][hf+1], apll[kb][hf+1]);
        }

        // ---- PV: 3-pass split, both branches ----
        #pragma unroll
        for (int kb = 0; kb < 4; kb++) {
            #pragma unroll
            for (int nb = 0; nb < 8; nb++) {
                uint32_t bvh[2], bvl[2];
                const uint32_t vaddr = (uint32_t)((kb*16 + la)*RSTRIDE + nb*16);
                ldsm_x2t(bvh, vh_b + vaddr);
                ldsm_x2t(bvl, vl_b + vaddr);
                mma16816(cg[nb], apgh[kb], bvh);
                mma16816(cg[nb], apgh[kb], bvl);
                mma16816(cg[nb], apgl[kb], bvh);
                mma16816(cl[nb], aplh[kb], bvh);
                mma16816(cl[nb], aplh[kb], bvl);
                mma16816(cl[nb], apll[kb], bvh);
            }
        }
    }

    // ---- row-sum reduction across quad ----
    lg0 += __shfl_xor_sync(0xffffffffu, lg0, 1); lg0 += __shfl_xor_sync(0xffffffffu, lg0, 2);
    lg1 += __shfl_xor_sync(0xffffffffu, lg1, 1); lg1 += __shfl_xor_sync(0xffffffffu, lg1, 2);
    ll0 += __shfl_xor_sync(0xffffffffu, ll0, 1); ll0 += __shfl_xor_sync(0xffffffffu, ll0, 2);
    ll1 += __shfl_xor_sync(0xffffffffu, ll1, 1); ll1 += __shfl_xor_sync(0xffffffffu, ll1, 2);

    // ---- gate + writeout ----
    const float gLo = gate[((size_t)(b*NH_ + h))*S_ + qrowLo];
    const float gHi = gate[((size_t)(b*NH_ + h))*S_ + qrowLo + 8];
    const float igLo = (1.f - gLo) / lg0, ilLo = gLo / ll0;
    const float igHi = (1.f - gHi) / lg1, ilHi = gHi / ll1;
    float* oLo = out + ((size_t)(b*S_ + qrowLo))*H_ + h*DH_ + (lane & 3)*2;
    float* oHi = oLo + 8*H_;
    #pragma unroll
    for (int nb = 0; nb < 8; nb++) {
        float2 a, c2;
        a.x  = cl[nb][0]*ilLo + cg[nb][0]*igLo;
        a.y  = cl[nb][1]*ilLo + cg[nb][1]*igLo;
        c2.x = cl[nb][2]*ilHi + cg[nb][2]*igHi;
        c2.y = cl[nb][3]*ilHi + cg[nb][3]*igHi;
        *(float2*)(oLo + nb*8) = a;
        *(float2*)(oHi + nb*8) = c2;
    }
}

// ---------------------------------------------------------------------------
extern "C" void kernel_launch(void* const* d_in, const int* in_sizes, int n_in,
                              void* d_out, int out_size)
{
    const float* X     = (const float*)d_in[0];
    const float* amask = (const float*)d_in[1];
    const int*   lmask = (const int*)  d_in[2];
    const float* gate  = (const float*)d_in[3];
    const float* Wq    = (const float*)d_in[4];
    const float* bq    = (const float*)d_in[5];
    const float* Wk    = (const float*)d_in[6];
    const float* bk    = (const float*)d_in[7];
    const float* Wv    = (const float*)d_in[8];
    const float* bv    = (const float*)d_in[9];
    float* out = (float*)d_out;

    // 1) pre-split X and W to bf16 h/l
    cvt_split<<<(B_*S_*H_/4 + 255)/256, 256>>>((const float4*)X,  0, B_*S_*H_/4);
    cvt_split<<<(H_*H_/4 + 255)/256,   256>>>((const float4*)Wq, 1, H_*H_/4);
    cvt_split<<<(H_*H_/4 + 255)/256,   256>>>((const float4*)Wk, 2, H_*H_/4);
    cvt_split<<<(H_*H_/4 + 255)/256,   256>>>((const float4*)Wv, 3, H_*H_/4);

    // 2) QKV projection on tensor cores -> split bf16 q/k/v
    cudaFuncSetAttribute(qkv_hmma, cudaFuncAttributeMaxDynamicSharedMemorySize, G_SMEM);
    dim3 g1(H_/128, (B_*S_)/128, 3);
    qkv_hmma<<<g1, 256, G_SMEM>>>(bq, bk, bv);

    // 3) dual-branch attention
    cudaFuncSetAttribute(attn_mma, cudaFuncAttributeMaxDynamicSharedMemorySize, SM_BYTES);
    dim3 g2(NH_, S_/128, B_);
    attn_mma<<<g2, 256, SM_BYTES>>>(amask, lmask, gate, out);
}

// round 7
// speedup vs baseline: 12.5913x; 2.1120x over previous
#include <cuda_runtime.h>
#include <cuda_fp16.h>
#include <math.h>
#include <stdint.h>

// Inputs:
// 0 hidden_states f32 [2,2048,1024]
// 1 attention_mask f32 [2,1,1,2048]
// 2 local_attention_mask i32 [2,1,2048,2048]
// 3 gate_outputs f32 [2,16,2048,1]
// 4 Wq 5 bq 6 Wk 7 bk 8 Wv 9 bv
// out f32 [2,2048,1024]

#define B_  2
#define S_  2048
#define H_  1024
#define NH_ 16
#define DH_ 64
#define SCALE_Q 0.18033688011112042f   // 0.125 * log2(e)

// fp16 scratch (device globals; no allocation allowed)
__device__ __half g_xh[(size_t)B_*S_*H_];
__device__ __half g_wh[3][(size_t)H_*H_];
__device__ __half g_qh[(size_t)B_*NH_*S_*DH_];
__device__ __half g_kh[(size_t)B_*NH_*S_*DH_];
__device__ __half g_vh[(size_t)B_*NH_*S_*DH_];

// ===================== helpers =====================
__device__ __forceinline__ uint32_t smem_u32(const void* p) {
    uint32_t a;
    asm("{ .reg .u64 t; cvta.to.shared.u64 t, %1; cvt.u32.u64 %0, t; }" : "=r"(a) : "l"(p));
    return a;
}
__device__ __forceinline__ float ex2f(float x) {
    float y; asm("ex2.approx.f32 %0, %1;" : "=f"(y) : "f"(x)); return y;
}
// pack two f32 -> f16x2 (lo=a, hi=b)
__device__ __forceinline__ uint32_t pack2(float a, float b) {
    uint32_t h;
    asm("cvt.rn.f16x2.f32 %0, %1, %2;" : "=r"(h) : "f"(b), "f"(a));
    return h;
}
__device__ __forceinline__ void ldsm_x4(uint32_t* r, uint32_t a) {
    asm volatile("ldmatrix.sync.aligned.m8n8.x4.shared.b16 {%0,%1,%2,%3}, [%4];"
        : "=r"(r[0]), "=r"(r[1]), "=r"(r[2]), "=r"(r[3]) : "r"(a));
}
__device__ __forceinline__ void ldsm_x2(uint32_t* r, uint32_t a) {
    asm volatile("ldmatrix.sync.aligned.m8n8.x2.shared.b16 {%0,%1}, [%2];"
        : "=r"(r[0]), "=r"(r[1]) : "r"(a));
}
__device__ __forceinline__ void ldsm_x2t(uint32_t* r, uint32_t a) {
    asm volatile("ldmatrix.sync.aligned.m8n8.x2.trans.shared.b16 {%0,%1}, [%2];"
        : "=r"(r[0]), "=r"(r[1]) : "r"(a));
}
__device__ __forceinline__ void mma16816(float* c, const uint32_t* a, const uint32_t* b) {
    asm volatile("mma.sync.aligned.m16n8k16.row.col.f32.f16.f16.f32 "
        "{%0,%1,%2,%3}, {%4,%5,%6,%7}, {%8,%9}, {%0,%1,%2,%3};"
        : "+f"(c[0]), "+f"(c[1]), "+f"(c[2]), "+f"(c[3])
        : "r"(a[0]), "r"(a[1]), "r"(a[2]), "r"(a[3]), "r"(b[0]), "r"(b[1]));
}
#define CPASYNC(dst, src) \
    asm volatile("cp.async.cg.shared.global [%0], [%1], 16;" :: "r"(dst), "l"(src))
#define CPCOMMIT() asm volatile("cp.async.commit_group;" ::: "memory")
#define CPWAIT(n)  asm volatile("cp.async.wait_group %0;" :: "n"(n) : "memory")

// ---------------------------------------------------------------------------
// fp32 -> fp16 converter.  which: 0=X, 1..3=Wq/Wk/Wv
// ---------------------------------------------------------------------------
__global__ __launch_bounds__(256) void cvt_h(const float4* __restrict__ src, int which, int n4)
{
    int i = blockIdx.x * 256 + threadIdx.x;
    if (i >= n4) return;
    uint2* dh = (which == 0) ? (uint2*)g_xh : (uint2*)g_wh[which-1];
    float4 f = src[i];
    dh[i] = make_uint2(pack2(f.x, f.y), pack2(f.z, f.w));
}

// ---------------------------------------------------------------------------
// QKV projection via fp16 HMMA (1-pass):  out = fp16(X @ W^T + b), [B,NH,S,DH];
// Q additionally scaled by log2e/8.
// BM=128, BN=128, BK=32; 8 warps (2m x 4n); double-buffered cp.async smem.
// ---------------------------------------------------------------------------
#define GS 80                 // smem row stride bytes (32 f16 = 64 B + 16 pad)
#define GXH(buf) ((buf)*20480 + 0)
#define GWH(buf) ((buf)*20480 + 10240)
#define G_SMEM  40960

__global__ __launch_bounds__(256, 2) void qkv_hmma(
    const float* __restrict__ bq, const float* __restrict__ bk_,
    const float* __restrict__ bv)
{
    extern __shared__ char smem[];
    const uint32_t sb = smem_u32(smem);
    const int tid  = threadIdx.x;
    const int lane = tid & 31;
    const int wid  = tid >> 5;
    const int wm   = wid >> 2;        // 0..1
    const int wn   = wid & 3;         // 0..3
    const int z    = blockIdx.z;
    const int m0   = blockIdx.y * 128;
    const int n0   = blockIdx.x * 128;

    const __half* xh = g_xh;
    const __half* wh = g_wh[z];
    const float* bias = (z == 0) ? bq : (z == 1) ? bk_ : bv;
    __half* oh = (z == 0) ? g_qh : (z == 1) ? g_kh : g_vh;

    // tile copy: 2 arrays x 512 chunks(16B) -> 2 chunks/thread/array
    auto issue_copy = [&](int buf, int k0) {
        #pragma unroll
        for (int u = 0; u < 2; u++) {
            const int chunk = tid*2 + u;       // 0..511
            const int row = chunk >> 2, c16 = chunk & 3;
            const uint32_t so = (uint32_t)(row*GS + c16*16);
            CPASYNC(sb + GXH(buf) + so, (const char*)(xh + (size_t)(m0+row)*H_ + k0 + c16*8));
            CPASYNC(sb + GWH(buf) + so, (const char*)(wh + (size_t)(n0+row)*H_ + k0 + c16*8));
        }
        CPCOMMIT();
    };

    float c[4][4][4];
    #pragma unroll
    for (int mi = 0; mi < 4; mi++)
        #pragma unroll
        for (int ni = 0; ni < 4; ni++)
            #pragma unroll
            for (int e = 0; e < 4; e++) c[mi][ni][e] = 0.f;

    issue_copy(0, 0);

    const int la = lane & 15;
    const int NSTEP = H_ / 32;                 // 32
    for (int t = 0; t < NSTEP; t++) {
        __syncthreads();
        if (t + 1 < NSTEP) { issue_copy((t+1)&1, (t+1)*32); CPWAIT(1); }
        else               { CPWAIT(0); }
        __syncthreads();

        const uint32_t xh_b = sb + GXH(t&1);
        const uint32_t wh_b = sb + GWH(t&1);
        #pragma unroll
        for (int kk = 0; kk < 2; kk++) {
            uint32_t Ah[4][4], Bh[4][2];
            #pragma unroll
            for (int mi = 0; mi < 4; mi++) {
                const uint32_t ao = (uint32_t)((wm*64 + mi*16 + la)*GS + kk*32 + (lane>>4)*16);
                ldsm_x4(Ah[mi], xh_b + ao);
            }
            #pragma unroll
            for (int ni = 0; ni < 4; ni++) {
                const uint32_t bo = (uint32_t)((wn*32 + ni*8 + (la & 7))*GS + kk*32 + (la>>3)*16);
                ldsm_x2(Bh[ni], wh_b + bo);
            }
            #pragma unroll
            for (int mi = 0; mi < 4; mi++)
                #pragma unroll
                for (int ni = 0; ni < 4; ni++)
                    mma16816(c[mi][ni], Ah[mi], Bh[ni]);
        }
    }

    // epilogue: +bias, (scale if Q), fp16 pack, [B,NH,S,DH]
    const float sc = (z == 0) ? SCALE_Q : 1.f;
    #pragma unroll
    for (int ni = 0; ni < 4; ni++) {
        const int nb_ = n0 + wn*32 + ni*8 + (lane & 3)*2;
        const float b0 = bias[nb_], b1 = bias[nb_ + 1];
        const int hh = nb_ >> 6, d = nb_ & 63;
        #pragma unroll
        for (int mi = 0; mi < 4; mi++) {
            #pragma unroll
            for (int half = 0; half < 2; half++) {
                const int r = m0 + wm*64 + mi*16 + (lane >> 2) + half*8;
                const int bI = r >> 11, s = r & (S_ - 1);
                float v0 = (c[mi][ni][half*2 + 0] + b0) * sc;
                float v1 = (c[mi][ni][half*2 + 1] + b1) * sc;
                const size_t pidx = ((((size_t)bI*NH_ + hh)*S_ + s)*DH_ + d) >> 1;
                ((uint32_t*)oh)[pidx] = pack2(v0, v1);
            }
        }
    }
}

// ---------------------------------------------------------------------------
// mma.sync fp16 dual-branch flash attention (1-pass fp16, no online max).
// 128 threads = 4 warps, 64 q-rows per CTA; 3 CTAs/SM for overlap.
// K/V tiles double-buffered via cp.async; fp32 ctx accumulators across tiles.
// ---------------------------------------------------------------------------
#define EA_OFF 0              // 2048 f32 = 8192
#define QH_OFF 8192           // 64*144 = 9216
#define KV_OFF 17408
#define KVB    18432          // per-buffer span (K 9216 + V 9216)
#define VH_O   9216
#define SM_BYTES 54272
#define RSTRIDE 144           // 64 f16 = 128 B + 16 pad

__global__ __launch_bounds__(128, 3) void attn_mma(
    const float* __restrict__ amask, const int* __restrict__ lmask,
    const float* __restrict__ gate,  float* __restrict__ out)
{
    extern __shared__ char smem[];
    const uint32_t sb = smem_u32(smem);
    float* ea_s = (float*)smem;

    const int tid  = threadIdx.x;
    const int lane = tid & 31;
    const int h  = blockIdx.x;
    const int qt = blockIdx.y;        // 64-row q tile
    const int b  = blockIdx.z;
    const size_t base = ((size_t)(b*NH_ + h)) * S_ * DH_;

    // ---- ea = exp(amask) ----
    #pragma unroll
    for (int i = 0; i < 16; i++)
        ea_s[tid + 128*i] = __expf(amask[b*S_ + tid + 128*i]);

    // ---- Q tile -> smem (pre-scaled fp16) ----
    #pragma unroll
    for (int u = 0; u < 4; u++) {
        const int idx = tid*4 + u;             // 0..511
        const int row = idx >> 3, c16 = idx & 7;
        uint4 v = *(const uint4*)(g_qh + base + (size_t)(qt*64 + row)*DH_ + c16*8);
        *(uint4*)(smem + QH_OFF + row*RSTRIDE + c16*16) = v;
    }

    // ---- K/V async copy ----
    auto issue_kv = [&](int buf, int kt) {
        const uint32_t bb = sb + KV_OFF + buf*KVB;
        #pragma unroll
        for (int u = 0; u < 4; u++) {
            const int chunk = tid*4 + u;       // 0..511
            const int row = chunk >> 3, c16 = chunk & 7;
            const uint32_t so = (uint32_t)(row*RSTRIDE + c16*16);
            const size_t go = base + (size_t)(kt + row)*DH_ + c16*8;
            CPASYNC(bb + so,        (const char*)(g_kh + go));
            CPASYNC(bb + VH_O + so, (const char*)(g_vh + go));
        }
        CPCOMMIT();
    };

    // per-thread fragment coordinates
    const int qr0 = (tid >> 5) * 16;
    const int qrowLo = qt*64 + qr0 + (lane >> 2);
    const int* mLo = lmask + ((size_t)b*S_ + qrowLo)*S_ + (lane & 3)*2;
    const int* mHi = mLo + 8*S_;

    float cg[8][4], cl[8][4];
    #pragma unroll
    for (int nb = 0; nb < 8; nb++)
        #pragma unroll
        for (int e = 0; e < 4; e++) { cg[nb][e] = 0.f; cl[nb][e] = 0.f; }
    float lg0 = 0.f, lg1 = 0.f, ll0 = 0.f, ll1 = 0.f;

    issue_kv(0, 0);

    const int la = lane & 15;
    const int NT = S_ / 64;                    // 32
    for (int t = 0; t < NT; t++) {
        const int kt = t * 64;
        __syncthreads();
        if (t + 1 < NT) { issue_kv((t+1)&1, kt + 64); CPWAIT(1); }
        else            { CPWAIT(0); }
        __syncthreads();

        const uint32_t kh_b = sb + KV_OFF + (t&1)*KVB;
        const uint32_t vh_b = kh_b + VH_O;

        // ---- prefetch local-mask bits ----
        int2 mkLo[8], mkHi[8];
        #pragma unroll
        for (int nb = 0; nb < 8; nb++) {
            mkLo[nb] = *(const int2*)&mLo[kt + nb*8];
            mkHi[nb] = *(const int2*)&mHi[kt + nb*8];
        }

        // ---- QK^T (1-pass fp16) ----
        float p[8][4];
        #pragma unroll
        for (int nb = 0; nb < 8; nb++)
            #pragma unroll
            for (int e = 0; e < 4; e++) p[nb][e] = 0.f;

        #pragma unroll
        for (int kb = 0; kb < 4; kb++) {
            uint32_t aqh[4];
            const uint32_t qaddr = (uint32_t)((qr0 + la)*RSTRIDE + kb*32 + (lane >> 4)*16);
            ldsm_x4(aqh, sb + QH_OFF + qaddr);
            #pragma unroll
            for (int nb = 0; nb < 8; nb++) {
                uint32_t bh[2];
                const uint32_t kaddr = (uint32_t)((nb*8 + (la & 7))*RSTRIDE + kb*32 + (la >> 3)*16);
                ldsm_x2(bh, kh_b + kaddr);
                mma16816(p[nb], aqh, bh);
            }
        }

        // ---- softmax + fragment repack (plain fp16 pack) ----
        uint32_t apg[4][4], apl[4][4];
        #pragma unroll
        for (int nb = 0; nb < 8; nb++) {
            const int col = kt + nb*8 + (lane & 3)*2;
            float2 ee = *(const float2*)&ea_s[col];
            float e0 = ex2f(p[nb][0]);
            float e1 = ex2f(p[nb][1]);
            float e2 = ex2f(p[nb][2]);
            float e3 = ex2f(p[nb][3]);
            float g0 = e0*ee.x, g1 = e1*ee.y, g2 = e2*ee.x, g3 = e3*ee.y;
            float l0 = mkLo[nb].x ? e0 : 0.f;
            float l1 = mkLo[nb].y ? e1 : 0.f;
            float l2 = mkHi[nb].x ? e2 : 0.f;
            float l3 = mkHi[nb].y ? e3 : 0.f;
            lg0 += g0 + g1; lg1 += g2 + g3;
            ll0 += l0 + l1; ll1 += l2 + l3;
            const int kb = nb >> 1, hf = (nb & 1) * 2;
            apg[kb][hf+0] = pack2(g0, g1);
            apg[kb][hf+1] = pack2(g2, g3);
            apl[kb][hf+0] = pack2(l0, l1);
            apl[kb][hf+1] = pack2(l2, l3);
        }

        // ---- PV (1-pass fp16), both branches ----
        #pragma unroll
        for (int kb = 0; kb < 4; kb++) {
            #pragma unroll
            for (int nb = 0; nb < 8; nb++) {
                uint32_t bvh[2];
                const uint32_t vaddr = (uint32_t)((kb*16 + la)*RSTRIDE + nb*16);
                ldsm_x2t(bvh, vh_b + vaddr);
                mma16816(cg[nb], apg[kb], bvh);
                mma16816(cl[nb], apl[kb], bvh);
            }
        }
    }

    // ---- row-sum reduction across quad ----
    lg0 += __shfl_xor_sync(0xffffffffu, lg0, 1); lg0 += __shfl_xor_sync(0xffffffffu, lg0, 2);
    lg1 += __shfl_xor_sync(0xffffffffu, lg1, 1); lg1 += __shfl_xor_sync(0xffffffffu, lg1, 2);
    ll0 += __shfl_xor_sync(0xffffffffu, ll0, 1); ll0 += __shfl_xor_sync(0xffffffffu, ll0, 2);
    ll1 += __shfl_xor_sync(0xffffffffu, ll1, 1); ll1 += __shfl_xor_sync(0xffffffffu, ll1, 2);

    // ---- gate + writeout ----
    const float gLo = gate[((size_t)(b*NH_ + h))*S_ + qrowLo];
    const float gHi = gate[((size_t)(b*NH_ + h))*S_ + qrowLo + 8];
    const float igLo = (1.f - gLo) / lg0, ilLo = gLo / ll0;
    const float igHi = (1.f - gHi) / lg1, ilHi = gHi / ll1;
    float* oLo = out + ((size_t)(b*S_ + qrowLo))*H_ + h*DH_ + (lane & 3)*2;
    float* oHi = oLo + 8*H_;
    #pragma unroll
    for (int nb = 0; nb < 8; nb++) {
        float2 a, c2;
        a.x  = cl[nb][0]*ilLo + cg[nb][0]*igLo;
        a.y  = cl[nb][1]*ilLo + cg[nb][1]*igLo;
        c2.x = cl[nb][2]*ilHi + cg[nb][2]*igHi;
        c2.y = cl[nb][3]*ilHi + cg[nb][3]*igHi;
        *(float2*)(oLo + nb*8) = a;
        *(float2*)(oHi + nb*8) = c2;
    }
}

// ---------------------------------------------------------------------------
extern "C" void kernel_launch(void* const* d_in, const int* in_sizes, int n_in,
                              void* d_out, int out_size)
{
    const float* X     = (const float*)d_in[0];
    const float* amask = (const float*)d_in[1];
    const int*   lmask = (const int*)  d_in[2];
    const float* gate  = (const float*)d_in[3];
    const float* Wq    = (const float*)d_in[4];
    const float* bq    = (const float*)d_in[5];
    const float* Wk    = (const float*)d_in[6];
    const float* bk    = (const float*)d_in[7];
    const float* Wv    = (const float*)d_in[8];
    const float* bv    = (const float*)d_in[9];
    float* out = (float*)d_out;

    // 1) X, W -> fp16
    cvt_h<<<(B_*S_*H_/4 + 255)/256, 256>>>((const float4*)X,  0, B_*S_*H_/4);
    cvt_h<<<(H_*H_/4 + 255)/256,   256>>>((const float4*)Wq, 1, H_*H_/4);
    cvt_h<<<(H_*H_/4 + 255)/256,   256>>>((const float4*)Wk, 2, H_*H_/4);
    cvt_h<<<(H_*H_/4 + 255)/256,   256>>>((const float4*)Wv, 3, H_*H_/4);

    // 2) QKV projection on tensor cores -> fp16 q/k/v
    cudaFuncSetAttribute(qkv_hmma, cudaFuncAttributeMaxDynamicSharedMemorySize, G_SMEM);
    dim3 g1(H_/128, (B_*S_)/128, 3);
    qkv_hmma<<<g1, 256, G_SMEM>>>(bq, bk, bv);

    // 3) dual-branch attention
    cudaFuncSetAttribute(attn_mma, cudaFuncAttributeMaxDynamicSharedMemorySize, SM_BYTES);
    dim3 g2(NH_, S_/64, B_);
    attn_mma<<<g2, 128, SM_BYTES>>>(amask, lmask, gate, out);
}

// round 8
// speedup vs baseline: 14.9290x; 1.1857x over previous
#include <cuda_runtime.h>
#include <cuda_fp16.h>
#include <math.h>
#include <stdint.h>

// Inputs:
// 0 hidden_states f32 [2,2048,1024]
// 1 attention_mask f32 [2,1,1,2048]
// 2 local_attention_mask i32 [2,1,2048,2048]
// 3 gate_outputs f32 [2,16,2048,1]
// 4 Wq 5 bq 6 Wk 7 bk 8 Wv 9 bv
// out f32 [2,2048,1024]

#define B_  2
#define S_  2048
#define H_  1024
#define NH_ 16
#define DH_ 64
#define SCALE_Q 0.18033688011112042f   // 0.125 * log2(e)

// fp16 scratch (device globals; no allocation allowed)
__device__ __half g_xh[(size_t)B_*S_*H_];
__device__ __half g_wh[3][(size_t)H_*H_];
__device__ __half g_qh[(size_t)B_*NH_*S_*DH_];
__device__ __half g_kh[(size_t)B_*NH_*S_*DH_];
__device__ __half g_vh[(size_t)B_*NH_*S_*DH_];
__device__ unsigned long long g_lm[(size_t)B_*S_*32];   // bit-packed local mask

// ===================== helpers =====================
__device__ __forceinline__ uint32_t smem_u32(const void* p) {
    uint32_t a;
    asm("{ .reg .u64 t; cvta.to.shared.u64 t, %1; cvt.u32.u64 %0, t; }" : "=r"(a) : "l"(p));
    return a;
}
__device__ __forceinline__ float ex2f(float x) {
    float y; asm("ex2.approx.f32 %0, %1;" : "=f"(y) : "f"(x)); return y;
}
// pack two f32 -> f16x2 (lo=a, hi=b)
__device__ __forceinline__ uint32_t pack2(float a, float b) {
    uint32_t h;
    asm("cvt.rn.f16x2.f32 %0, %1, %2;" : "=r"(h) : "f"(b), "f"(a));
    return h;
}
__device__ __forceinline__ void ldsm_x4(uint32_t* r, uint32_t a) {
    asm volatile("ldmatrix.sync.aligned.m8n8.x4.shared.b16 {%0,%1,%2,%3}, [%4];"
        : "=r"(r[0]), "=r"(r[1]), "=r"(r[2]), "=r"(r[3]) : "r"(a));
}
__device__ __forceinline__ void ldsm_x4t(uint32_t* r, uint32_t a) {
    asm volatile("ldmatrix.sync.aligned.m8n8.x4.trans.shared.b16 {%0,%1,%2,%3}, [%4];"
        : "=r"(r[0]), "=r"(r[1]), "=r"(r[2]), "=r"(r[3]) : "r"(a));
}
__device__ __forceinline__ void mma16816(float* c, const uint32_t* a, const uint32_t* b) {
    asm volatile("mma.sync.aligned.m16n8k16.row.col.f32.f16.f16.f32 "
        "{%0,%1,%2,%3}, {%4,%5,%6,%7}, {%8,%9}, {%0,%1,%2,%3};"
        : "+f"(c[0]), "+f"(c[1]), "+f"(c[2]), "+f"(c[3])
        : "r"(a[0]), "r"(a[1]), "r"(a[2]), "r"(a[3]), "r"(b[0]), "r"(b[1]));
}
#define CPASYNC(dst, src) \
    asm volatile("cp.async.cg.shared.global [%0], [%1], 16;" :: "r"(dst), "l"(src))
#define CPCOMMIT() asm volatile("cp.async.commit_group;" ::: "memory")
#define CPWAIT(n)  asm volatile("cp.async.wait_group %0;" :: "n"(n) : "memory")

// ---------------------------------------------------------------------------
// Bit-pack the local mask: [B,S,S] int32 -> [B,S,S/64] uint64.
// ---------------------------------------------------------------------------
__global__ __launch_bounds__(256) void pack_mask(const int* __restrict__ lmask)
{
    const int i = blockIdx.x * 256 + threadIdx.x;      // 0 .. B*S*32-1
    const int row = i >> 5, seg = i & 31;
    const int4* p = (const int4*)(lmask + ((size_t)row << 11) + seg * 64);
    unsigned long long m = 0ull;
    #pragma unroll
    for (int u = 0; u < 16; u++) {
        int4 v = p[u];
        m |= ((unsigned long long)(v.x != 0)) << (u*4 + 0);
        m |= ((unsigned long long)(v.y != 0)) << (u*4 + 1);
        m |= ((unsigned long long)(v.z != 0)) << (u*4 + 2);
        m |= ((unsigned long long)(v.w != 0)) << (u*4 + 3);
    }
    g_lm[i] = m;
}

// ---------------------------------------------------------------------------
// fp32 -> fp16 converter, fused for X + Wq + Wk + Wv (one launch).
// ---------------------------------------------------------------------------
#define XN4 (B_*S_*H_/4)
#define WN4 (H_*H_/4)
__global__ __launch_bounds__(256) void cvt_all(
    const float4* __restrict__ X,  const float4* __restrict__ Wq,
    const float4* __restrict__ Wk, const float4* __restrict__ Wv)
{
    int i = blockIdx.x * 256 + threadIdx.x;
    const float4* src;
    uint2* dst;
    if (i < XN4)              { src = X;  dst = (uint2*)g_xh;    }
    else if (i < XN4 + WN4)   { src = Wq; dst = (uint2*)g_wh[0]; i -= XN4; }
    else if (i < XN4 + 2*WN4) { src = Wk; dst = (uint2*)g_wh[1]; i -= XN4 + WN4; }
    else if (i < XN4 + 3*WN4) { src = Wv; dst = (uint2*)g_wh[2]; i -= XN4 + 2*WN4; }
    else return;
    float4 f = src[i];
    dst[i] = make_uint2(pack2(f.x, f.y), pack2(f.z, f.w));
}

// ---------------------------------------------------------------------------
// QKV projection via fp16 HMMA (1-pass):  out = fp16(X @ W^T + b), [B,NH,S,DH];
// Q additionally scaled by log2e/8.
// BM=128, BN=128, BK=32; 8 warps (2m x 4n); double-buffered cp.async smem.
// ---------------------------------------------------------------------------
#define GS 80                 // smem row stride bytes (32 f16 = 64 B + 16 pad)
#define GXH(buf) ((buf)*20480 + 0)
#define GWH(buf) ((buf)*20480 + 10240)
#define G_SMEM  40960

__global__ __launch_bounds__(256, 2) void qkv_hmma(
    const float* __restrict__ bq, const float* __restrict__ bk_,
    const float* __restrict__ bv)
{
    extern __shared__ char smem[];
    const uint32_t sb = smem_u32(smem);
    const int tid  = threadIdx.x;
    const int lane = tid & 31;
    const int wid  = tid >> 5;
    const int wm   = wid >> 2;        // 0..1
    const int wn   = wid & 3;         // 0..3
    const int z    = blockIdx.z;
    const int m0   = blockIdx.y * 128;
    const int n0   = blockIdx.x * 128;

    const __half* xh = g_xh;
    const __half* wh = g_wh[z];
    const float* bias = (z == 0) ? bq : (z == 1) ? bk_ : bv;
    __half* oh = (z == 0) ? g_qh : (z == 1) ? g_kh : g_vh;

    // tile copy: 2 arrays x 512 chunks(16B) -> 2 chunks/thread/array
    auto issue_copy = [&](int buf, int k0) {
        #pragma unroll
        for (int u = 0; u < 2; u++) {
            const int chunk = tid*2 + u;       // 0..511
            const int row = chunk >> 2, c16 = chunk & 3;
            const uint32_t so = (uint32_t)(row*GS + c16*16);
            CPASYNC(sb + GXH(buf) + so, (const char*)(xh + (size_t)(m0+row)*H_ + k0 + c16*8));
            CPASYNC(sb + GWH(buf) + so, (const char*)(wh + (size_t)(n0+row)*H_ + k0 + c16*8));
        }
        CPCOMMIT();
    };

    float c[4][4][4];
    #pragma unroll
    for (int mi = 0; mi < 4; mi++)
        #pragma unroll
        for (int ni = 0; ni < 4; ni++)
            #pragma unroll
            for (int e = 0; e < 4; e++) c[mi][ni][e] = 0.f;

    issue_copy(0, 0);

    const int la = lane & 15;
    const int NSTEP = H_ / 32;                 // 32
    for (int t = 0; t < NSTEP; t++) {
        __syncthreads();
        if (t + 1 < NSTEP) { issue_copy((t+1)&1, (t+1)*32); CPWAIT(1); }
        else               { CPWAIT(0); }
        __syncthreads();

        const uint32_t xh_b = sb + GXH(t&1);
        const uint32_t wh_b = sb + GWH(t&1);
        #pragma unroll
        for (int kk = 0; kk < 2; kk++) {
            uint32_t Ah[4][4], Bh[2][4];
            #pragma unroll
            for (int mi = 0; mi < 4; mi++) {
                const uint32_t ao = (uint32_t)((wm*64 + mi*16 + la)*GS + kk*32 + (lane>>4)*16);
                ldsm_x4(Ah[mi], xh_b + ao);
            }
            #pragma unroll
            for (int ni2 = 0; ni2 < 2; ni2++) {
                const uint32_t bo = (uint32_t)((wn*32 + ni2*16 + ((lane>>4)<<3) + (lane & 7))*GS
                                               + kk*32 + ((lane>>3)&1)*16);
                ldsm_x4(Bh[ni2], wh_b + bo);
            }
            #pragma unroll
            for (int mi = 0; mi < 4; mi++)
                #pragma unroll
                for (int ni2 = 0; ni2 < 2; ni2++) {
                    mma16816(c[mi][2*ni2],     Ah[mi], Bh[ni2]);
                    mma16816(c[mi][2*ni2 + 1], Ah[mi], Bh[ni2] + 2);
                }
        }
    }

    // epilogue: +bias, (scale if Q), fp16 pack, [B,NH,S,DH]
    const float sc = (z == 0) ? SCALE_Q : 1.f;
    #pragma unroll
    for (int ni = 0; ni < 4; ni++) {
        const int nb_ = n0 + wn*32 + ni*8 + (lane & 3)*2;
        const float b0 = bias[nb_], b1 = bias[nb_ + 1];
        const int hh = nb_ >> 6, d = nb_ & 63;
        #pragma unroll
        for (int mi = 0; mi < 4; mi++) {
            #pragma unroll
            for (int half = 0; half < 2; half++) {
                const int r = m0 + wm*64 + mi*16 + (lane >> 2) + half*8;
                const int bI = r >> 11, s = r & (S_ - 1);
                float v0 = (c[mi][ni][half*2 + 0] + b0) * sc;
                float v1 = (c[mi][ni][half*2 + 1] + b1) * sc;
                const size_t pidx = ((((size_t)bI*NH_ + hh)*S_ + s)*DH_ + d) >> 1;
                ((uint32_t*)oh)[pidx] = pack2(v0, v1);
            }
        }
    }
}

// ---------------------------------------------------------------------------
// mma.sync fp16 dual-branch flash attention (1-pass fp16, no online max).
// 128 threads = 4 warps, 64 q-rows per CTA; 3 CTAs/SM.
// K/V double-buffered cp.async; bit-packed local mask (2 LDG.64/thread/tile);
// paired x4 ldmatrix for K and V (36 LDSM/warp/tile).
// ---------------------------------------------------------------------------
#define EA_OFF 0              // 2048 f32 = 8192
#define QH_OFF 8192           // 64*144 = 9216
#define KV_OFF 17408
#define KVB    18432          // per-buffer span (K 9216 + V 9216)
#define VH_O   9216
#define SM_BYTES 54272
#define RSTRIDE 144           // 64 f16 = 128 B + 16 pad

__global__ __launch_bounds__(128, 3) void attn_mma(
    const float* __restrict__ amask, const float* __restrict__ gate,
    float* __restrict__ out)
{
    extern __shared__ char smem[];
    const uint32_t sb = smem_u32(smem);
    float* ea_s = (float*)smem;

    const int tid  = threadIdx.x;
    const int lane = tid & 31;
    const int h  = blockIdx.x;
    const int qt = blockIdx.y;        // 64-row q tile
    const int b  = blockIdx.z;
    const size_t base = ((size_t)(b*NH_ + h)) * S_ * DH_;

    // ---- ea = exp(amask) ----
    #pragma unroll
    for (int i = 0; i < 16; i++)
        ea_s[tid + 128*i] = __expf(amask[b*S_ + tid + 128*i]);

    // ---- Q tile -> smem (pre-scaled fp16) ----
    #pragma unroll
    for (int u = 0; u < 4; u++) {
        const int idx = tid*4 + u;             // 0..511
        const int row = idx >> 3, c16 = idx & 7;
        uint4 v = *(const uint4*)(g_qh + base + (size_t)(qt*64 + row)*DH_ + c16*8);
        *(uint4*)(smem + QH_OFF + row*RSTRIDE + c16*16) = v;
    }

    // ---- K/V async copy ----
    auto issue_kv = [&](int buf, int kt) {
        const uint32_t bb = sb + KV_OFF + buf*KVB;
        #pragma unroll
        for (int u = 0; u < 4; u++) {
            const int chunk = tid*4 + u;       // 0..511
            const int row = chunk >> 3, c16 = chunk & 7;
            const uint32_t so = (uint32_t)(row*RSTRIDE + c16*16);
            const size_t go = base + (size_t)(kt + row)*DH_ + c16*8;
            CPASYNC(bb + so,        (const char*)(g_kh + go));
            CPASYNC(bb + VH_O + so, (const char*)(g_vh + go));
        }
        CPCOMMIT();
    };

    // per-thread fragment coordinates
    const int qr0 = (tid >> 5) * 16;
    const int qrowLo = qt*64 + qr0 + (lane >> 2);
    const unsigned long long* pmLo = g_lm + ((size_t)b*S_ + qrowLo)*32;
    const unsigned long long* pmHi = pmLo + 8*32;
    const int shb = (lane & 3) * 2;            // bit offset within 8-bit nb group

    float cg[8][4], cl[8][4];
    #pragma unroll
    for (int nb = 0; nb < 8; nb++)
        #pragma unroll
        for (int e = 0; e < 4; e++) { cg[nb][e] = 0.f; cl[nb][e] = 0.f; }
    float lg0 = 0.f, lg1 = 0.f, ll0 = 0.f, ll1 = 0.f;

    issue_kv(0, 0);

    const int la = lane & 15;
    const int NT = S_ / 64;                    // 32
    for (int t = 0; t < NT; t++) {
        const int kt = t * 64;
        __syncthreads();
        if (t + 1 < NT) { issue_kv((t+1)&1, kt + 64); CPWAIT(1); }
        else            { CPWAIT(0); }
        __syncthreads();

        const uint32_t kh_b = sb + KV_OFF + (t&1)*KVB;
        const uint32_t vh_b = kh_b + VH_O;

        // ---- bit-packed local mask for this tile (2 LDG.64) ----
        const unsigned long long mb64Lo = pmLo[t];
        const unsigned long long mb64Hi = pmHi[t];
        const uint32_t mLo0 = (uint32_t)mb64Lo, mLo1 = (uint32_t)(mb64Lo >> 32);
        const uint32_t mHi0 = (uint32_t)mb64Hi, mHi1 = (uint32_t)(mb64Hi >> 32);

        // ---- QK^T (paired x4 ldmatrix for K) ----
        float p[8][4];
        #pragma unroll
        for (int nb = 0; nb < 8; nb++)
            #pragma unroll
            for (int e = 0; e < 4; e++) p[nb][e] = 0.f;

        #pragma unroll
        for (int kb = 0; kb < 4; kb++) {
            uint32_t aqh[4];
            const uint32_t qaddr = (uint32_t)((qr0 + la)*RSTRIDE + kb*32 + (lane >> 4)*16);
            ldsm_x4(aqh, sb + QH_OFF + qaddr);
            #pragma unroll
            for (int nb2 = 0; nb2 < 4; nb2++) {
                uint32_t b4[4];
                const uint32_t kaddr = (uint32_t)((nb2*16 + ((lane>>4)<<3) + (lane & 7))*RSTRIDE
                                                  + kb*32 + ((lane>>3)&1)*16);
                ldsm_x4(b4, kh_b + kaddr);
                mma16816(p[2*nb2],     aqh, b4);
                mma16816(p[2*nb2 + 1], aqh, b4 + 2);
            }
        }

        // ---- softmax + fragment repack (mask bits from registers) ----
        uint32_t apg[4][4], apl[4][4];
        #pragma unroll
        for (int nb = 0; nb < 8; nb++) {
            const int col = kt + nb*8 + (lane & 3)*2;
            float2 ee = *(const float2*)&ea_s[col];
            float e0 = ex2f(p[nb][0]);
            float e1 = ex2f(p[nb][1]);
            float e2 = ex2f(p[nb][2]);
            float e3 = ex2f(p[nb][3]);
            float g0 = e0*ee.x, g1 = e1*ee.y, g2 = e2*ee.x, g3 = e3*ee.y;
            const uint32_t wLo = (nb < 4) ? mLo0 : mLo1;
            const uint32_t wHi = (nb < 4) ? mHi0 : mHi1;
            const int sh = (nb & 3)*8 + shb;
            float l0 = ((wLo >> sh)     & 1u) ? e0 : 0.f;
            float l1 = ((wLo >> (sh+1)) & 1u) ? e1 : 0.f;
            float l2 = ((wHi >> sh)     & 1u) ? e2 : 0.f;
            float l3 = ((wHi >> (sh+1)) & 1u) ? e3 : 0.f;
            lg0 += g0 + g1; lg1 += g2 + g3;
            ll0 += l0 + l1; ll1 += l2 + l3;
            const int kb = nb >> 1, hf = (nb & 1) * 2;
            apg[kb][hf+0] = pack2(g0, g1);
            apg[kb][hf+1] = pack2(g2, g3);
            apl[kb][hf+0] = pack2(l0, l1);
            apl[kb][hf+1] = pack2(l2, l3);
        }

        // ---- PV (paired x4.trans ldmatrix for V), both branches ----
        #pragma unroll
        for (int kb = 0; kb < 4; kb++) {
            #pragma unroll
            for (int nb2 = 0; nb2 < 4; nb2++) {
                uint32_t v4[4];
                const uint32_t vaddr = (uint32_t)((kb*16 + ((lane>>3)&1)*8 + (lane & 7))*RSTRIDE
                                                  + nb2*32 + (lane >> 4)*16);
                ldsm_x4t(v4, vh_b + vaddr);
                mma16816(cg[2*nb2],     apg[kb], v4);
                mma16816(cl[2*nb2],     apl[kb], v4);
                mma16816(cg[2*nb2 + 1], apg[kb], v4 + 2);
                mma16816(cl[2*nb2 + 1], apl[kb], v4 + 2);
            }
        }
    }

    // ---- row-sum reduction across quad ----
    lg0 += __shfl_xor_sync(0xffffffffu, lg0, 1); lg0 += __shfl_xor_sync(0xffffffffu, lg0, 2);
    lg1 += __shfl_xor_sync(0xffffffffu, lg1, 1); lg1 += __shfl_xor_sync(0xffffffffu, lg1, 2);
    ll0 += __shfl_xor_sync(0xffffffffu, ll0, 1); ll0 += __shfl_xor_sync(0xffffffffu, ll0, 2);
    ll1 += __shfl_xor_sync(0xffffffffu, ll1, 1); ll1 += __shfl_xor_sync(0xffffffffu, ll1, 2);

    // ---- gate + writeout ----
    const float gLo = gate[((size_t)(b*NH_ + h))*S_ + qrowLo];
    const float gHi = gate[((size_t)(b*NH_ + h))*S_ + qrowLo + 8];
    const float igLo = (1.f - gLo) / lg0, ilLo = gLo / ll0;
    const float igHi = (1.f - gHi) / lg1, ilHi = gHi / ll1;
    float* oLo = out + ((size_t)(b*S_ + qrowLo))*H_ + h*DH_ + (lane & 3)*2;
    float* oHi = oLo + 8*H_;
    #pragma unroll
    for (int nb = 0; nb < 8; nb++) {
        float2 a, c2;
        a.x  = cl[nb][0]*ilLo + cg[nb][0]*igLo;
        a.y  = cl[nb][1]*ilLo + cg[nb][1]*igLo;
        c2.x = cl[nb][2]*ilHi + cg[nb][2]*igHi;
        c2.y = cl[nb][3]*ilHi + cg[nb][3]*igHi;
        *(float2*)(oLo + nb*8) = a;
        *(float2*)(oHi + nb*8) = c2;
    }
}

// ---------------------------------------------------------------------------
extern "C" void kernel_launch(void* const* d_in, const int* in_sizes, int n_in,
                              void* d_out, int out_size)
{
    const float* X     = (const float*)d_in[0];
    const float* amask = (const float*)d_in[1];
    const int*   lmask = (const int*)  d_in[2];
    const float* gate  = (const float*)d_in[3];
    const float* Wq    = (const float*)d_in[4];
    const float* bq    = (const float*)d_in[5];
    const float* Wk    = (const float*)d_in[6];
    const float* bk    = (const float*)d_in[7];
    const float* Wv    = (const float*)d_in[8];
    const float* bv    = (const float*)d_in[9];
    float* out = (float*)d_out;

    // 1) bit-pack local mask + convert X/W to fp16 (2 launches)
    pack_mask<<<(B_*S_*32)/256, 256>>>(lmask);
    cvt_all<<<(XN4 + 3*WN4 + 255)/256, 256>>>(
        (const float4*)X, (const float4*)Wq, (const float4*)Wk, (const float4*)Wv);

    // 2) QKV projection on tensor cores -> fp16 q/k/v
    cudaFuncSetAttribute(qkv_hmma, cudaFuncAttributeMaxDynamicSharedMemorySize, G_SMEM);
    dim3 g1(H_/128, (B_*S_)/128, 3);
    qkv_hmma<<<g1, 256, G_SMEM>>>(bq, bk, bv);

    // 3) dual-branch attention
    cudaFuncSetAttribute(attn_mma, cudaFuncAttributeMaxDynamicSharedMemorySize, SM_BYTES);
    dim3 g2(NH_, S_/64, B_);
    attn_mma<<<g2, 128, SM_BYTES>>>(amask, gate, out);
}